// round 5
// baseline (speedup 1.0000x reference)
#include <cuda_runtime.h>
#include <cstdint>

// ---------------- static scratch (no allocations allowed) ----------------
// All atomics in this file target ONLY these __device__ statics.
// d_out (harness buffer) receives plain stores exclusively.
#define MAXN 100000
__device__ float g_dinv[MAXN];            // deg -> rsqrt(deg)
__device__ float g_agg [MAXN * 128];      // agg_x -> layer2 agg -> final out copy
__device__ float g_out1[MAXN * 256];      // layer-1 output; later proj hidden
__device__ float g_h2  [MAXN * 128];      // out1 @ W2 (pre-aggregation)

// ---------------- small helpers ----------------
__global__ void k_fill1(float* p, int n) {
    int i = blockIdx.x * blockDim.x + threadIdx.x;
    if (i < n) p[i] = 1.0f;   // self-loop contributes 1 to every degree
}

__global__ void k_count(const int* __restrict__ dst, float* deg, int E) {
    int e = blockIdx.x * blockDim.x + threadIdx.x;
    if (e < E) atomicAdd(&deg[dst[e]], 1.0f);
}

__global__ void k_rsqrt(float* p, int n) {
    int i = blockIdx.x * blockDim.x + threadIdx.x;
    if (i < n) p[i] = rsqrtf(p[i]);
}

// out[row] = h[row] * dinv[row]^2   (self-loop term), 1 float4 per thread
__global__ void k_selfloop(const float* __restrict__ h,
                           const float* __restrict__ dinv,
                           float* __restrict__ out, int n4) {
    int i = blockIdx.x * blockDim.x + threadIdx.x;
    if (i >= n4) return;
    int row = i >> 5;                 // 32 float4 per 128-wide row
    float s = dinv[row]; s *= s;
    float4 v = reinterpret_cast<const float4*>(h)[i];
    v.x *= s; v.y *= s; v.z *= s; v.w *= s;
    reinterpret_cast<float4*>(out)[i] = v;
}

// one warp per edge: out[dst] += h[src] * (dinv[src]*dinv[dst]); D = 128
// out MUST be a __device__ scratch buffer (atomics).
__global__ void k_edge(const int* __restrict__ src,
                       const int* __restrict__ dst,
                       const float* __restrict__ dinv,
                       const float* __restrict__ h,
                       float* __restrict__ out, int E) {
    int g = blockIdx.x * blockDim.x + threadIdx.x;
    int w = g >> 5, lane = g & 31;
    if (w >= E) return;
    int s = src[w];
    int d = dst[w];
    float r = dinv[s] * dinv[d];
    float4 v = reinterpret_cast<const float4*>(h + (size_t)s * 128)[lane];
    float* o = out + (size_t)d * 128 + lane * 4;
    atomicAdd(o + 0, v.x * r);
    atomicAdd(o + 1, v.y * r);
    atomicAdd(o + 2, v.z * r);
    atomicAdd(o + 3, v.w * r);
}

// y = prelu(y + bias) in place, AND mirror result to y2 (plain stores).
__global__ void k_bias_prelu_dual(float* __restrict__ y, const float* __restrict__ b,
                                  const float* __restrict__ ap,
                                  float* __restrict__ y2, int n4) {
    int i = blockIdx.x * blockDim.x + threadIdx.x;
    if (i >= n4) return;
    float a = *ap;
    int c = (i & 31) * 4;
    float4 bb = *reinterpret_cast<const float4*>(b + c);
    float4 v = reinterpret_cast<float4*>(y)[i];
    v.x += bb.x; v.y += bb.y; v.z += bb.z; v.w += bb.w;
    v.x = v.x >= 0.f ? v.x : a * v.x;
    v.y = v.y >= 0.f ? v.y : a * v.y;
    v.z = v.z >= 0.f ? v.z : a * v.z;
    v.w = v.w >= 0.f ? v.w : a * v.w;
    reinterpret_cast<float4*>(y)[i]  = v;
    reinterpret_cast<float4*>(y2)[i] = v;
}

// ---------------- register-blocked SGEMM: C = epi(A @ B) ----------------
// A: [M,K] row-major, B: [K,N] row-major. BM=BN=128, BK=8, 8x8 thread tile.
// EPI: 0 raw  1 prelu(acc+bias)  2 relu(acc+bias)  3 acc+bias
//      4 C=acc AND C2=acc*dinv[row]^2
template <int EPI>
__global__ __launch_bounds__(256) void sgemm128(
    int M, int N, int K,
    const float* __restrict__ A, const float* __restrict__ B,
    const float* __restrict__ bias, const float* __restrict__ prelu_a,
    const float* __restrict__ dinv,
    float* __restrict__ C, float* __restrict__ C2)
{
    constexpr int BM = 128, BN = 128, BK = 8, TM = 8, TN = 8;
    __shared__ float As[BK][BM];
    __shared__ float Bs[BK][BN];

    const int tid  = threadIdx.x;
    const int tcol = tid % (BN / TN);   // 0..15
    const int trow = tid / (BN / TN);   // 0..15

    const int a_row  = tid >> 1;              // 0..127
    const int a_col4 = (tid & 1) * 4;         // 0 or 4
    const int b_row  = tid >> 5;              // 0..7
    const int b_col4 = (tid & 31) * 4;        // 0..124

    const int gRowBase = blockIdx.y * BM;
    const int gColBase = blockIdx.x * BN;

    float acc[TM][TN] = {};
    float regM[TM], regN[TN];

    for (int k0 = 0; k0 < K; k0 += BK) {
        int arow = gRowBase + a_row;
        float4 av = make_float4(0.f, 0.f, 0.f, 0.f);
        if (arow < M)
            av = *reinterpret_cast<const float4*>(&A[(size_t)arow * K + k0 + a_col4]);
        As[a_col4 + 0][a_row] = av.x;
        As[a_col4 + 1][a_row] = av.y;
        As[a_col4 + 2][a_row] = av.z;
        As[a_col4 + 3][a_row] = av.w;

        float4 bv = *reinterpret_cast<const float4*>(
            &B[(size_t)(k0 + b_row) * N + gColBase + b_col4]);
        *reinterpret_cast<float4*>(&Bs[b_row][b_col4]) = bv;

        __syncthreads();
#pragma unroll
        for (int k = 0; k < BK; k++) {
#pragma unroll
            for (int i = 0; i < TM; i++) regM[i] = As[k][trow * TM + i];
#pragma unroll
            for (int j = 0; j < TN; j++) regN[j] = Bs[k][tcol * TN + j];
#pragma unroll
            for (int i = 0; i < TM; i++)
#pragma unroll
                for (int j = 0; j < TN; j++)
                    acc[i][j] = fmaf(regM[i], regN[j], acc[i][j]);
        }
        __syncthreads();
    }

    float a_val = 0.f;
    if (EPI == 1) a_val = *prelu_a;

    const int colBase = gColBase + tcol * TN;
#pragma unroll
    for (int i = 0; i < TM; i++) {
        int row = gRowBase + trow * TM + i;
        if (row >= M) break;      // rows in thread tile are contiguous
        float v[TN];
#pragma unroll
        for (int j = 0; j < TN; j++) v[j] = acc[i][j];

        if (EPI == 1 || EPI == 2 || EPI == 3) {
#pragma unroll
            for (int j = 0; j < TN; j++) v[j] += bias[colBase + j];
        }
        if (EPI == 1) {
#pragma unroll
            for (int j = 0; j < TN; j++) v[j] = v[j] >= 0.f ? v[j] : a_val * v[j];
        }
        if (EPI == 2) {
#pragma unroll
            for (int j = 0; j < TN; j++) v[j] = fmaxf(v[j], 0.f);
        }

        float* cp = &C[(size_t)row * N + colBase];
        *reinterpret_cast<float4*>(cp)     = make_float4(v[0], v[1], v[2], v[3]);
        *reinterpret_cast<float4*>(cp + 4) = make_float4(v[4], v[5], v[6], v[7]);

        if (EPI == 4) {
            float s = dinv[row]; s *= s;
            float* cp2 = &C2[(size_t)row * N + colBase];
            *reinterpret_cast<float4*>(cp2) =
                make_float4(v[0] * s, v[1] * s, v[2] * s, v[3] * s);
            *reinterpret_cast<float4*>(cp2 + 4) =
                make_float4(v[4] * s, v[5] * s, v[6] * s, v[7] * s);
        }
    }
}

// ---------------- launch ----------------
extern "C" void kernel_launch(void* const* d_in, const int* in_sizes, int n_in,
                              void* d_out, int out_size) {
    const float* x    = (const float*)d_in[0];
    const int*   ei   = (const int*)d_in[1];     // int32! (JAX x64 disabled)
    const float* W1   = (const float*)d_in[2];
    const float* b1   = (const float*)d_in[3];
    const float* W2   = (const float*)d_in[4];
    const float* b2   = (const float*)d_in[5];
    const float* a    = (const float*)d_in[6];
    const float* fc1w = (const float*)d_in[7];
    const float* fc1b = (const float*)d_in[8];
    const float* fc2w = (const float*)d_in[9];
    const float* fc2b = (const float*)d_in[10];

    const int N = in_sizes[0] / 128;      // 100000 nodes
    const int E = in_sizes[1] / 2;        // 1600000 edges
    const int* src = ei;
    const int* dst = ei + E;

    float* out  = (float*)d_out;                    // [N,128]  (plain stores only)
    float* proj = out + (size_t)N * 128;            // [N,128]  (plain stores only)

    float *pd, *pagg, *pout1, *ph2;
    cudaGetSymbolAddress((void**)&pd,    g_dinv);
    cudaGetSymbolAddress((void**)&pagg,  g_agg);
    cudaGetSymbolAddress((void**)&pout1, g_out1);
    cudaGetSymbolAddress((void**)&ph2,   g_h2);

    const int TPB = 256;
    const int n4  = N * 32;                         // float4 count for [N,128]

    // 1) degrees -> dinv  (atomics into device scratch)
    k_fill1<<<(N + TPB - 1) / TPB, TPB>>>(pd, N);
    k_count<<<(E + TPB - 1) / TPB, TPB>>>(dst, pd, E);
    k_rsqrt<<<(N + TPB - 1) / TPB, TPB>>>(pd, N);

    // 2) agg_x = A_hat @ x  into g_agg (self-loop init + edge scatter)
    k_selfloop<<<(n4 + TPB - 1) / TPB, TPB>>>(x, pd, pagg, n4);
    {
        long long threads = (long long)E * 32;
        k_edge<<<(int)((threads + TPB - 1) / TPB), TPB>>>(src, dst, pd, x, pagg, E);
    }

    dim3 gemm_grid1(2, (N + 127) / 128);    // 256 output cols
    dim3 gemm_grid2(1, (N + 127) / 128);    // 128 output cols

    // 3) out1 = prelu(agg_x @ W1 + b1)   [N,256]   (g_agg free afterwards)
    sgemm128<1><<<gemm_grid1, 256>>>(N, 256, 128, pagg, W1, b1, a, nullptr, pout1, nullptr);

    // 4) h2 = out1 @ W2 ; g_agg seeded with h2*dinv^2 (self-loop term)
    sgemm128<4><<<gemm_grid2, 256>>>(N, 128, 256, pout1, W2, nullptr, nullptr, pd, ph2, pagg);

    // 5) edge scatter of h2 into g_agg (device scratch), then bias+prelu:
    //    finalize in g_agg and mirror to d_out with plain stores.
    {
        long long threads = (long long)E * 32;
        k_edge<<<(int)((threads + TPB - 1) / TPB), TPB>>>(src, dst, pd, ph2, pagg, E);
    }
    k_bias_prelu_dual<<<(n4 + TPB - 1) / TPB, TPB>>>(pagg, b2, a, out, n4);

    // 6) proj head (reads device-resident copy in g_agg):
    //    hidden = relu(out @ fc1 + b) into g_out1 ; proj = hidden @ fc2 + b into d_out
    sgemm128<2><<<gemm_grid2, 256>>>(N, 128, 128, pagg, fc1w, fc1b, nullptr, nullptr, pout1, nullptr);
    sgemm128<3><<<gemm_grid2, 256>>>(N, 128, 128, pout1, fc2w, fc2b, nullptr, nullptr, proj, nullptr);
}

// round 6
// speedup vs baseline: 1.4234x; 1.4234x over previous
#include <cuda_runtime.h>
#include <cstdint>

// ---------------- static scratch (no allocations allowed) ----------------
#define MAXN 100000
__device__ float g_dinv[MAXN];            // deg -> rsqrt(deg)
__device__ float g_agg [MAXN * 128];      // agg_x -> layer2 agg -> final out copy
__device__ float g_out1[MAXN * 256];      // layer-1 output; later proj hidden
__device__ float g_h2  [MAXN * 128];      // out1 @ W2 (pre-aggregation)

// ---------------- small helpers ----------------
__global__ void k_fill1(float* p, int n) {
    int i = blockIdx.x * blockDim.x + threadIdx.x;
    if (i < n) p[i] = 1.0f;   // self-loop contributes 1 to every degree
}

__global__ void k_count(const int* __restrict__ dst, float* deg, int E) {
    int e = blockIdx.x * blockDim.x + threadIdx.x;
    if (e < E) atomicAdd(&deg[dst[e]], 1.0f);
}

__global__ void k_rsqrt(float* p, int n) {
    int i = blockIdx.x * blockDim.x + threadIdx.x;
    if (i < n) p[i] = rsqrtf(p[i]);
}

// out[row] = h[row] * dinv[row]^2   (self-loop term), 1 float4 per thread
__global__ void k_selfloop(const float* __restrict__ h,
                           const float* __restrict__ dinv,
                           float* __restrict__ out, int n4) {
    int i = blockIdx.x * blockDim.x + threadIdx.x;
    if (i >= n4) return;
    int row = i >> 5;                 // 32 float4 per 128-wide row
    float s = dinv[row]; s *= s;
    float4 v = reinterpret_cast<const float4*>(h)[i];
    v.x *= s; v.y *= s; v.z *= s; v.w *= s;
    reinterpret_cast<float4*>(out)[i] = v;
}

// one warp per edge: out[dst] += h[src] * (dinv[src]*dinv[dst]); D = 128
// vector RED: 1 LDG.128 + 1 RED.128 per lane. out = device scratch only.
__global__ void k_edge(const int* __restrict__ src,
                       const int* __restrict__ dst,
                       const float* __restrict__ dinv,
                       const float* __restrict__ h,
                       float* __restrict__ out, int E) {
    int g = blockIdx.x * blockDim.x + threadIdx.x;
    int w = g >> 5, lane = g & 31;
    if (w >= E) return;
    int s = src[w];
    int d = dst[w];
    float r = dinv[s] * dinv[d];
    float4 v = reinterpret_cast<const float4*>(h + (size_t)s * 128)[lane];
    v.x *= r; v.y *= r; v.z *= r; v.w *= r;
#if __CUDA_ARCH__ >= 900
    atomicAdd(reinterpret_cast<float4*>(out + (size_t)d * 128 + lane * 4), v);
#else
    float* o = out + (size_t)d * 128 + lane * 4;
    atomicAdd(o + 0, v.x); atomicAdd(o + 1, v.y);
    atomicAdd(o + 2, v.z); atomicAdd(o + 3, v.w);
#endif
}

// y = prelu(y + bias) in place, AND mirror result to y2 (plain stores).
__global__ void k_bias_prelu_dual(float* __restrict__ y, const float* __restrict__ b,
                                  const float* __restrict__ ap,
                                  float* __restrict__ y2, int n4) {
    int i = blockIdx.x * blockDim.x + threadIdx.x;
    if (i >= n4) return;
    float a = *ap;
    int c = (i & 31) * 4;
    float4 bb = *reinterpret_cast<const float4*>(b + c);
    float4 v = reinterpret_cast<float4*>(y)[i];
    v.x += bb.x; v.y += bb.y; v.z += bb.z; v.w += bb.w;
    v.x = v.x >= 0.f ? v.x : a * v.x;
    v.y = v.y >= 0.f ? v.y : a * v.y;
    v.z = v.z >= 0.f ? v.z : a * v.z;
    v.w = v.w >= 0.f ? v.w : a * v.w;
    reinterpret_cast<float4*>(y)[i]  = v;
    reinterpret_cast<float4*>(y2)[i] = v;
}

// ------- software-pipelined register-blocked SGEMM: C = epi(A @ B) -------
// A: [M,K] row-major, B: [K,N] row-major. BM=BN=128, BK=8, 8x8 thread tile.
// Next K-tile is prefetched into registers during compute of current tile.
// EPI: 0 raw  1 prelu(acc+bias)  2 relu(acc+bias)  3 acc+bias
//      4 C=acc AND C2=acc*dinv[row]^2
template <int EPI>
__global__ __launch_bounds__(256) void sgemm128(
    int M, int N, int K,
    const float* __restrict__ A, const float* __restrict__ B,
    const float* __restrict__ bias, const float* __restrict__ prelu_a,
    const float* __restrict__ dinv,
    float* __restrict__ C, float* __restrict__ C2)
{
    constexpr int BM = 128, BN = 128, BK = 8, TM = 8, TN = 8;
    __shared__ float As[BK][BM];
    __shared__ float Bs[BK][BN];

    const int tid  = threadIdx.x;
    const int tcol = tid % (BN / TN);   // 0..15
    const int trow = tid / (BN / TN);   // 0..15

    const int a_row  = tid >> 1;              // 0..127
    const int a_col4 = (tid & 1) * 4;         // 0 or 4
    const int b_row  = tid >> 5;              // 0..7
    const int b_col4 = (tid & 31) * 4;        // 0..124

    const int gRowBase = blockIdx.y * BM;
    const int gColBase = blockIdx.x * BN;

    const int arow    = gRowBase + a_row;
    const bool a_ok   = arow < M;
    const float* Aptr = &A[(size_t)(a_ok ? arow : 0) * K + a_col4];
    const float* Bptr = &B[(size_t)b_row * N + gColBase + b_col4];

    float acc[TM][TN] = {};
    float regM[TM], regN[TN];

    // prologue: load first tile
    float4 av = a_ok ? *reinterpret_cast<const float4*>(Aptr)
                     : make_float4(0.f, 0.f, 0.f, 0.f);
    float4 bv = *reinterpret_cast<const float4*>(Bptr);

    for (int k0 = 0; k0 < K; k0 += BK) {
        // stage current tile into smem
        As[a_col4 + 0][a_row] = av.x;
        As[a_col4 + 1][a_row] = av.y;
        As[a_col4 + 2][a_row] = av.z;
        As[a_col4 + 3][a_row] = av.w;
        *reinterpret_cast<float4*>(&Bs[b_row][b_col4]) = bv;
        __syncthreads();

        // prefetch next tile into registers (overlaps with compute)
        if (k0 + BK < K) {
            av = a_ok ? *reinterpret_cast<const float4*>(Aptr + k0 + BK)
                      : make_float4(0.f, 0.f, 0.f, 0.f);
            bv = *reinterpret_cast<const float4*>(Bptr + (size_t)(k0 + BK) * N);
        }

#pragma unroll
        for (int k = 0; k < BK; k++) {
#pragma unroll
            for (int i = 0; i < TM; i++) regM[i] = As[k][trow * TM + i];
#pragma unroll
            for (int j = 0; j < TN; j++) regN[j] = Bs[k][tcol * TN + j];
#pragma unroll
            for (int i = 0; i < TM; i++)
#pragma unroll
                for (int j = 0; j < TN; j++)
                    acc[i][j] = fmaf(regM[i], regN[j], acc[i][j]);
        }
        __syncthreads();
    }

    float a_val = 0.f;
    if (EPI == 1) a_val = *prelu_a;

    const int colBase = gColBase + tcol * TN;
#pragma unroll
    for (int i = 0; i < TM; i++) {
        int row = gRowBase + trow * TM + i;
        if (row >= M) break;      // rows in thread tile are contiguous
        float v[TN];
#pragma unroll
        for (int j = 0; j < TN; j++) v[j] = acc[i][j];

        if (EPI == 1 || EPI == 2 || EPI == 3) {
#pragma unroll
            for (int j = 0; j < TN; j++) v[j] += bias[colBase + j];
        }
        if (EPI == 1) {
#pragma unroll
            for (int j = 0; j < TN; j++) v[j] = v[j] >= 0.f ? v[j] : a_val * v[j];
        }
        if (EPI == 2) {
#pragma unroll
            for (int j = 0; j < TN; j++) v[j] = fmaxf(v[j], 0.f);
        }

        float* cp = &C[(size_t)row * N + colBase];
        *reinterpret_cast<float4*>(cp)     = make_float4(v[0], v[1], v[2], v[3]);
        *reinterpret_cast<float4*>(cp + 4) = make_float4(v[4], v[5], v[6], v[7]);

        if (EPI == 4) {
            float s = dinv[row]; s *= s;
            float* cp2 = &C2[(size_t)row * N + colBase];
            *reinterpret_cast<float4*>(cp2) =
                make_float4(v[0] * s, v[1] * s, v[2] * s, v[3] * s);
            *reinterpret_cast<float4*>(cp2 + 4) =
                make_float4(v[4] * s, v[5] * s, v[6] * s, v[7] * s);
        }
    }
}

// ---------------- launch ----------------
extern "C" void kernel_launch(void* const* d_in, const int* in_sizes, int n_in,
                              void* d_out, int out_size) {
    const float* x    = (const float*)d_in[0];
    const int*   ei   = (const int*)d_in[1];     // int32 (JAX x64 disabled)
    const float* W1   = (const float*)d_in[2];
    const float* b1   = (const float*)d_in[3];
    const float* W2   = (const float*)d_in[4];
    const float* b2   = (const float*)d_in[5];
    const float* a    = (const float*)d_in[6];
    const float* fc1w = (const float*)d_in[7];
    const float* fc1b = (const float*)d_in[8];
    const float* fc2w = (const float*)d_in[9];
    const float* fc2b = (const float*)d_in[10];

    const int N = in_sizes[0] / 128;      // 100000 nodes
    const int E = in_sizes[1] / 2;        // 1600000 edges
    const int* src = ei;
    const int* dst = ei + E;

    float* out  = (float*)d_out;                    // [N,128]  (plain stores only)
    float* proj = out + (size_t)N * 128;            // [N,128]  (plain stores only)

    float *pd, *pagg, *pout1, *ph2;
    cudaGetSymbolAddress((void**)&pd,    g_dinv);
    cudaGetSymbolAddress((void**)&pagg,  g_agg);
    cudaGetSymbolAddress((void**)&pout1, g_out1);
    cudaGetSymbolAddress((void**)&ph2,   g_h2);

    const int TPB = 256;
    const int n4  = N * 32;                         // float4 count for [N,128]

    // 1) degrees -> dinv  (atomics into device scratch)
    k_fill1<<<(N + TPB - 1) / TPB, TPB>>>(pd, N);
    k_count<<<(E + TPB - 1) / TPB, TPB>>>(dst, pd, E);
    k_rsqrt<<<(N + TPB - 1) / TPB, TPB>>>(pd, N);

    // 2) agg_x = A_hat @ x  into g_agg (self-loop init + edge scatter)
    k_selfloop<<<(n4 + TPB - 1) / TPB, TPB>>>(x, pd, pagg, n4);
    {
        long long threads = (long long)E * 32;
        k_edge<<<(int)((threads + TPB - 1) / TPB), TPB>>>(src, dst, pd, x, pagg, E);
    }

    dim3 gemm_grid1(2, (N + 127) / 128);    // 256 output cols
    dim3 gemm_grid2(1, (N + 127) / 128);    // 128 output cols

    // 3) out1 = prelu(agg_x @ W1 + b1)   [N,256]   (g_agg free afterwards)
    sgemm128<1><<<gemm_grid1, 256>>>(N, 256, 128, pagg, W1, b1, a, nullptr, pout1, nullptr);

    // 4) h2 = out1 @ W2 ; g_agg seeded with h2*dinv^2 (self-loop term)
    sgemm128<4><<<gemm_grid2, 256>>>(N, 128, 256, pout1, W2, nullptr, nullptr, pd, ph2, pagg);

    // 5) edge scatter of h2 into g_agg, then bias+prelu: finalize in g_agg
    //    and mirror to d_out with plain stores.
    {
        long long threads = (long long)E * 32;
        k_edge<<<(int)((threads + TPB - 1) / TPB), TPB>>>(src, dst, pd, ph2, pagg, E);
    }
    k_bias_prelu_dual<<<(n4 + TPB - 1) / TPB, TPB>>>(pagg, b2, a, out, n4);

    // 6) proj head: hidden = relu(out @ fc1 + b) into g_out1 ;
    //    proj = hidden @ fc2 + b into d_out
    sgemm128<2><<<gemm_grid2, 256>>>(N, 128, 128, pagg, fc1w, fc1b, nullptr, nullptr, pout1, nullptr);
    sgemm128<3><<<gemm_grid2, 256>>>(N, 128, 128, pout1, fc2w, fc2b, nullptr, nullptr, proj, nullptr);
}

// round 7
// speedup vs baseline: 2.1779x; 1.5300x over previous
#include <cuda_runtime.h>
#include <cstdint>

// ---------------- static scratch (no allocations allowed) ----------------
#define MAXN 100000
__device__ float g_dinv[MAXN];            // deg -> rsqrt(deg)
__device__ float g_agg [MAXN * 128];      // agg_x -> layer2 agg -> final out copy
__device__ float g_out1[MAXN * 256];      // layer-1 output; later proj hidden
__device__ float g_h2  [MAXN * 128];      // out1 @ W2 (pre-aggregation)

// ---------------- small helpers ----------------
__global__ void k_fill1(float* p, int n) {
    int i = blockIdx.x * blockDim.x + threadIdx.x;
    if (i < n) p[i] = 1.0f;   // self-loop contributes 1 to every degree
}

__global__ void k_count(const int* __restrict__ dst, float* deg, int E) {
    int e = blockIdx.x * blockDim.x + threadIdx.x;
    if (e < E) atomicAdd(&deg[dst[e]], 1.0f);
}

__global__ void k_rsqrt(float* p, int n) {
    int i = blockIdx.x * blockDim.x + threadIdx.x;
    if (i < n) p[i] = rsqrtf(p[i]);
}

// out[row] = h[row] * dinv[row]^2   (self-loop term), 1 float4 per thread
__global__ void k_selfloop(const float* __restrict__ h,
                           const float* __restrict__ dinv,
                           float* __restrict__ out, int n4) {
    int i = blockIdx.x * blockDim.x + threadIdx.x;
    if (i >= n4) return;
    int row = i >> 5;                 // 32 float4 per 128-wide row
    float s = dinv[row]; s *= s;
    float4 v = reinterpret_cast<const float4*>(h)[i];
    v.x *= s; v.y *= s; v.z *= s; v.w *= s;
    reinterpret_cast<float4*>(out)[i] = v;
}

// one warp per edge: out[dst] += h[src] * (dinv[src]*dinv[dst]); D = 128
__global__ void k_edge(const int* __restrict__ src,
                       const int* __restrict__ dst,
                       const float* __restrict__ dinv,
                       const float* __restrict__ h,
                       float* __restrict__ out, int E) {
    int g = blockIdx.x * blockDim.x + threadIdx.x;
    int w = g >> 5, lane = g & 31;
    if (w >= E) return;
    int s = src[w];
    int d = dst[w];
    float r = dinv[s] * dinv[d];
    float4 v = reinterpret_cast<const float4*>(h + (size_t)s * 128)[lane];
    v.x *= r; v.y *= r; v.z *= r; v.w *= r;
#if __CUDA_ARCH__ >= 900
    atomicAdd(reinterpret_cast<float4*>(out + (size_t)d * 128 + lane * 4), v);
#else
    float* o = out + (size_t)d * 128 + lane * 4;
    atomicAdd(o + 0, v.x); atomicAdd(o + 1, v.y);
    atomicAdd(o + 2, v.z); atomicAdd(o + 3, v.w);
#endif
}

// y = prelu(y + bias) in place, AND mirror result to y2 (plain stores).
__global__ void k_bias_prelu_dual(float* __restrict__ y, const float* __restrict__ b,
                                  const float* __restrict__ ap,
                                  float* __restrict__ y2, int n4) {
    int i = blockIdx.x * blockDim.x + threadIdx.x;
    if (i >= n4) return;
    float a = *ap;
    int c = (i & 31) * 4;
    float4 bb = *reinterpret_cast<const float4*>(b + c);
    float4 v = reinterpret_cast<float4*>(y)[i];
    v.x += bb.x; v.y += bb.y; v.z += bb.z; v.w += bb.w;
    v.x = v.x >= 0.f ? v.x : a * v.x;
    v.y = v.y >= 0.f ? v.y : a * v.y;
    v.z = v.z >= 0.f ? v.z : a * v.z;
    v.w = v.w >= 0.f ? v.w : a * v.w;
    reinterpret_cast<float4*>(y)[i]  = v;
    reinterpret_cast<float4*>(y2)[i] = v;
}

// ---------------- tf32 tensor-core GEMM: C = epi(A @ B) ----------------
// A: [M,K] row-major, B: [K,N] row-major.
// BM=BN=128, BK=16. 8 warps (2 M x 4 N), warp tile 64x32,
// mma.sync.m16n8k8 tf32. Smem stride 136 -> conflict-free fragment reads.
// EPI: 0 raw  1 prelu(acc+bias)  2 relu(acc+bias)  3 acc+bias
//      4 C=acc AND C2=acc*dinv[row]^2

__device__ __forceinline__ uint32_t f2tf32(float f) {
    uint32_t u;
    asm("cvt.rna.tf32.f32 %0, %1;" : "=r"(u) : "f"(f));
    return u;
}

__device__ __forceinline__ void mma_tf32(float* c, const uint32_t* a, const uint32_t* b) {
    asm volatile(
        "mma.sync.aligned.m16n8k8.row.col.f32.tf32.tf32.f32 "
        "{%0,%1,%2,%3}, {%4,%5,%6,%7}, {%8,%9}, {%0,%1,%2,%3};"
        : "+f"(c[0]), "+f"(c[1]), "+f"(c[2]), "+f"(c[3])
        : "r"(a[0]), "r"(a[1]), "r"(a[2]), "r"(a[3]),
          "r"(b[0]), "r"(b[1]));
}

template <int EPI>
__global__ __launch_bounds__(256) void tgemm128(
    int M, int N, int K,
    const float* __restrict__ A, const float* __restrict__ B,
    const float* __restrict__ bias, const float* __restrict__ prelu_a,
    const float* __restrict__ dinv,
    float* __restrict__ C, float* __restrict__ C2)
{
    constexpr int BM = 128, BN = 128, BK = 16;
    constexpr int LDSM = 136;   // padded stride (32b words): 136 mod 32 = 8
    __shared__ uint32_t As[BK * LDSM];   // [k][m]
    __shared__ uint32_t Bs[BK * LDSM];   // [k][n]

    const int tid  = threadIdx.x;
    const int lane = tid & 31;
    const int wid  = tid >> 5;
    const int g    = lane >> 2;          // groupID
    const int t    = lane & 3;           // threadID_in_group

    const int warpM = (wid & 1) * 64;    // 2 warps along M
    const int warpN = (wid >> 1) * 32;   // 4 warps along N

    const int gRow = blockIdx.y * BM;
    const int gCol = blockIdx.x * BN;

    float c[4][4][4];
#pragma unroll
    for (int mt = 0; mt < 4; mt++)
#pragma unroll
        for (int nt = 0; nt < 4; nt++)
#pragma unroll
            for (int i = 0; i < 4; i++) c[mt][nt][i] = 0.f;

    float4 avr[2], bvr[2];

    // ---- global tile loaders (register prefetch) ----
    auto loadA = [&](int k0, float4* r) {
#pragma unroll
        for (int i = 0; i < 2; i++) {
            int idx = tid + i * 256;            // 512 float4 per A tile
            int m = idx >> 2, kq = (idx & 3) << 2;
            int gm = gRow + m;
            r[i] = (gm < M)
                 ? *reinterpret_cast<const float4*>(&A[(size_t)gm * K + k0 + kq])
                 : make_float4(0.f, 0.f, 0.f, 0.f);
        }
    };
    auto loadB = [&](int k0, float4* r) {
#pragma unroll
        for (int i = 0; i < 2; i++) {
            int idx = tid + i * 256;            // 512 float4 per B tile
            int k = idx >> 5, n4 = (idx & 31) << 2;
            r[i] = *reinterpret_cast<const float4*>(&B[(size_t)(k0 + k) * N + gCol + n4]);
        }
    };
    auto stageA = [&](const float4* r) {
#pragma unroll
        for (int i = 0; i < 2; i++) {
            int idx = tid + i * 256;
            int m = idx >> 2, kq = (idx & 3) << 2;
            As[(kq + 0) * LDSM + m] = f2tf32(r[i].x);
            As[(kq + 1) * LDSM + m] = f2tf32(r[i].y);
            As[(kq + 2) * LDSM + m] = f2tf32(r[i].z);
            As[(kq + 3) * LDSM + m] = f2tf32(r[i].w);
        }
    };
    auto stageB = [&](const float4* r) {
#pragma unroll
        for (int i = 0; i < 2; i++) {
            int idx = tid + i * 256;
            int k = idx >> 5, n4 = (idx & 31) << 2;
            uint4 u = make_uint4(f2tf32(r[i].x), f2tf32(r[i].y),
                                 f2tf32(r[i].z), f2tf32(r[i].w));
            *reinterpret_cast<uint4*>(&Bs[k * LDSM + n4]) = u;
        }
    };

    loadA(0, avr); loadB(0, bvr);

    for (int k0 = 0; k0 < K; k0 += BK) {
        stageA(avr); stageB(bvr);
        __syncthreads();
        if (k0 + BK < K) { loadA(k0 + BK, avr); loadB(k0 + BK, bvr); }

#pragma unroll
        for (int kk = 0; kk < BK; kk += 8) {
            uint32_t af[4][4], bf[4][2];
#pragma unroll
            for (int mt = 0; mt < 4; mt++) {
                int m0 = warpM + mt * 16 + g;
                af[mt][0] = As[(kk + t    ) * LDSM + m0];
                af[mt][1] = As[(kk + t    ) * LDSM + m0 + 8];
                af[mt][2] = As[(kk + t + 4) * LDSM + m0];
                af[mt][3] = As[(kk + t + 4) * LDSM + m0 + 8];
            }
#pragma unroll
            for (int nt = 0; nt < 4; nt++) {
                int n0 = warpN + nt * 8 + g;
                bf[nt][0] = Bs[(kk + t    ) * LDSM + n0];
                bf[nt][1] = Bs[(kk + t + 4) * LDSM + n0];
            }
#pragma unroll
            for (int mt = 0; mt < 4; mt++)
#pragma unroll
                for (int nt = 0; nt < 4; nt++)
                    mma_tf32(c[mt][nt], af[mt], bf[nt]);
        }
        __syncthreads();
    }

    // ---- epilogue ----
    float a_val = 0.f;
    if (EPI == 1) a_val = *prelu_a;

#pragma unroll
    for (int mt = 0; mt < 4; mt++) {
        int r0 = gRow + warpM + mt * 16 + g;
        int r1 = r0 + 8;
        float s0 = 0.f, s1 = 0.f;
        if (EPI == 4) {
            if (r0 < M) { s0 = dinv[r0]; s0 *= s0; }
            if (r1 < M) { s1 = dinv[r1]; s1 *= s1; }
        }
#pragma unroll
        for (int nt = 0; nt < 4; nt++) {
            int col = gCol + warpN + nt * 8 + t * 2;
            float v0 = c[mt][nt][0], v1 = c[mt][nt][1];
            float v2 = c[mt][nt][2], v3 = c[mt][nt][3];

            if (EPI == 1 || EPI == 2 || EPI == 3) {
                float b0 = bias[col], b1 = bias[col + 1];
                v0 += b0; v1 += b1; v2 += b0; v3 += b1;
            }
            if (EPI == 1) {
                v0 = v0 >= 0.f ? v0 : a_val * v0;
                v1 = v1 >= 0.f ? v1 : a_val * v1;
                v2 = v2 >= 0.f ? v2 : a_val * v2;
                v3 = v3 >= 0.f ? v3 : a_val * v3;
            }
            if (EPI == 2) {
                v0 = fmaxf(v0, 0.f); v1 = fmaxf(v1, 0.f);
                v2 = fmaxf(v2, 0.f); v3 = fmaxf(v3, 0.f);
            }

            if (r0 < M)
                *reinterpret_cast<float2*>(&C[(size_t)r0 * N + col]) = make_float2(v0, v1);
            if (r1 < M)
                *reinterpret_cast<float2*>(&C[(size_t)r1 * N + col]) = make_float2(v2, v3);

            if (EPI == 4) {
                if (r0 < M)
                    *reinterpret_cast<float2*>(&C2[(size_t)r0 * N + col]) =
                        make_float2(v0 * s0, v1 * s0);
                if (r1 < M)
                    *reinterpret_cast<float2*>(&C2[(size_t)r1 * N + col]) =
                        make_float2(v2 * s1, v3 * s1);
            }
        }
    }
}

// ---------------- launch ----------------
extern "C" void kernel_launch(void* const* d_in, const int* in_sizes, int n_in,
                              void* d_out, int out_size) {
    const float* x    = (const float*)d_in[0];
    const int*   ei   = (const int*)d_in[1];     // int32 (JAX x64 disabled)
    const float* W1   = (const float*)d_in[2];
    const float* b1   = (const float*)d_in[3];
    const float* W2   = (const float*)d_in[4];
    const float* b2   = (const float*)d_in[5];
    const float* a    = (const float*)d_in[6];
    const float* fc1w = (const float*)d_in[7];
    const float* fc1b = (const float*)d_in[8];
    const float* fc2w = (const float*)d_in[9];
    const float* fc2b = (const float*)d_in[10];

    const int N = in_sizes[0] / 128;      // 100000 nodes
    const int E = in_sizes[1] / 2;        // 1600000 edges
    const int* src = ei;
    const int* dst = ei + E;

    float* out  = (float*)d_out;                    // [N,128]  (plain stores only)
    float* proj = out + (size_t)N * 128;            // [N,128]  (plain stores only)

    float *pd, *pagg, *pout1, *ph2;
    cudaGetSymbolAddress((void**)&pd,    g_dinv);
    cudaGetSymbolAddress((void**)&pagg,  g_agg);
    cudaGetSymbolAddress((void**)&pout1, g_out1);
    cudaGetSymbolAddress((void**)&ph2,   g_h2);

    const int TPB = 256;
    const int n4  = N * 32;                         // float4 count for [N,128]

    // 1) degrees -> dinv  (atomics into device scratch)
    k_fill1<<<(N + TPB - 1) / TPB, TPB>>>(pd, N);
    k_count<<<(E + TPB - 1) / TPB, TPB>>>(dst, pd, E);
    k_rsqrt<<<(N + TPB - 1) / TPB, TPB>>>(pd, N);

    // 2) agg_x = A_hat @ x  into g_agg (self-loop init + edge scatter)
    k_selfloop<<<(n4 + TPB - 1) / TPB, TPB>>>(x, pd, pagg, n4);
    {
        long long threads = (long long)E * 32;
        k_edge<<<(int)((threads + TPB - 1) / TPB), TPB>>>(src, dst, pd, x, pagg, E);
    }

    dim3 grid1(2, (N + 127) / 128);    // 256 output cols
    dim3 grid2(1, (N + 127) / 128);    // 128 output cols

    // 3) out1 = prelu(agg_x @ W1 + b1)   [N,256]
    tgemm128<1><<<grid1, 256>>>(N, 256, 128, pagg, W1, b1, a, nullptr, pout1, nullptr);

    // 4) h2 = out1 @ W2 ; g_agg seeded with h2*dinv^2 (self-loop term)
    tgemm128<4><<<grid2, 256>>>(N, 128, 256, pout1, W2, nullptr, nullptr, pd, ph2, pagg);

    // 5) edge scatter of h2 into g_agg, then bias+prelu: finalize in g_agg
    //    and mirror to d_out with plain stores.
    {
        long long threads = (long long)E * 32;
        k_edge<<<(int)((threads + TPB - 1) / TPB), TPB>>>(src, dst, pd, ph2, pagg, E);
    }
    k_bias_prelu_dual<<<(n4 + TPB - 1) / TPB, TPB>>>(pagg, b2, a, out, n4);

    // 6) proj head: hidden = relu(out @ fc1 + b) into g_out1 ;
    //    proj = hidden @ fc2 + b into d_out
    tgemm128<2><<<grid2, 256>>>(N, 128, 128, pagg, fc1w, fc1b, nullptr, nullptr, pout1, nullptr);
    tgemm128<3><<<grid2, 256>>>(N, 128, 128, pout1, fc2w, fc2b, nullptr, nullptr, proj, nullptr);
}

// round 8
// speedup vs baseline: 4.0061x; 1.8395x over previous
#include <cuda_runtime.h>
#include <cstdint>

// ---------------- static scratch (no allocations allowed) ----------------
#define MAXN 100000
#define MAXE 1600000
#define SCAN_B 1024
#define MAXNB ((MAXN + SCAN_B - 1) / SCAN_B)   // 98

__device__ float g_dinv[MAXN];
__device__ float g_agg [MAXN * 128];      // agg_x -> layer2 result copy
__device__ float g_out1[MAXN * 256];      // layer-1 output; later proj hidden
__device__ float g_h2  [MAXN * 128];      // out1 @ W2 (pre-aggregation)
__device__ int   g_deg [MAXN];            // in-degree histogram (no self-loop)
__device__ int   g_excl[MAXN];            // per-block exclusive scan
__device__ int   g_btot[128];             // block totals -> exclusive
__device__ int   g_rowp[MAXN + 1];        // CSR row pointers
__device__ int   g_cur [MAXN];            // fill cursors
__device__ int   g_csrc[MAXE];            // CSR src indices

// ---------------- CSR build ----------------
__global__ void k_hist(const int* __restrict__ dst, int* deg, int E) {
    int e = blockIdx.x * blockDim.x + threadIdx.x;
    if (e < E) atomicAdd(&deg[dst[e]], 1);
}

__global__ void k_scan_blocks(const int* __restrict__ deg, int* excl,
                              int* btot, int n) {
    __shared__ int sh[SCAN_B];
    int t = threadIdx.x;
    int i = blockIdx.x * SCAN_B + t;
    int v = (i < n) ? deg[i] : 0;
    sh[t] = v;
    __syncthreads();
    for (int off = 1; off < SCAN_B; off <<= 1) {
        int add = (t >= off) ? sh[t - off] : 0;
        __syncthreads();
        sh[t] += add;
        __syncthreads();
    }
    if (i < n) excl[i] = sh[t] - v;          // exclusive within block
    if (t == SCAN_B - 1) btot[blockIdx.x] = sh[t];
}

__global__ void k_scan_tops(int* btot, int nb) {   // 1 block, 128 threads
    __shared__ int sh[128];
    int t = threadIdx.x;
    int v = (t < nb) ? btot[t] : 0;
    sh[t] = v;
    __syncthreads();
    for (int off = 1; off < 128; off <<= 1) {
        int add = (t >= off) ? sh[t - off] : 0;
        __syncthreads();
        sh[t] += add;
        __syncthreads();
    }
    if (t < nb) btot[t] = sh[t] - v;         // exclusive block offsets
}

// row_ptr, cursor, dinv, row_ptr[n]
__global__ void k_finalize(const int* __restrict__ deg, const int* __restrict__ excl,
                           const int* __restrict__ btot,
                           int* rowp, int* cur, float* dinv, int n) {
    int i = blockIdx.x * blockDim.x + threadIdx.x;
    if (i >= n) return;
    int rp = excl[i] + btot[i >> 10];
    rowp[i] = rp;
    cur[i]  = rp;
    dinv[i] = rsqrtf((float)deg[i] + 1.0f);   // +1 self-loop
    if (i == n - 1) rowp[n] = rp + deg[i];
}

__global__ void k_fillcsr(const int* __restrict__ src, const int* __restrict__ dst,
                          int* cur, int* csrc, int E) {
    int e = blockIdx.x * blockDim.x + threadIdx.x;
    if (e >= E) return;
    int pos = atomicAdd(&cur[dst[e]], 1);
    csrc[pos] = src[e];
}

// ---------------- CSR aggregation: warp per dst node ----------------
// out_node = dinv[d] * ( dinv[d]*h[d] + sum_s dinv[s]*h[s] )
// FINAL: add bias, prelu, store to out AND out2 (d_out mirror).
template <bool FINAL>
__global__ void k_agg(const int* __restrict__ rowp, const int* __restrict__ csrc,
                      const float* __restrict__ dinv, const float* __restrict__ h,
                      float* __restrict__ out,
                      const float* __restrict__ bias, const float* __restrict__ ap,
                      float* __restrict__ out2, int n) {
    int gtid = blockIdx.x * blockDim.x + threadIdx.x;
    int d = gtid >> 5, lane = gtid & 31;
    if (d >= n) return;

    float dd = dinv[d];
    float4 acc = reinterpret_cast<const float4*>(h + (size_t)d * 128)[lane];
    acc.x *= dd; acc.y *= dd; acc.z *= dd; acc.w *= dd;

    int j = rowp[d], end = rowp[d + 1];
    for (; j + 4 <= end; j += 4) {
        int s0 = csrc[j], s1 = csrc[j + 1], s2 = csrc[j + 2], s3 = csrc[j + 3];
        float w0 = dinv[s0], w1 = dinv[s1], w2 = dinv[s2], w3 = dinv[s3];
        float4 v0 = reinterpret_cast<const float4*>(h + (size_t)s0 * 128)[lane];
        float4 v1 = reinterpret_cast<const float4*>(h + (size_t)s1 * 128)[lane];
        float4 v2 = reinterpret_cast<const float4*>(h + (size_t)s2 * 128)[lane];
        float4 v3 = reinterpret_cast<const float4*>(h + (size_t)s3 * 128)[lane];
        acc.x += w0 * v0.x + w1 * v1.x + w2 * v2.x + w3 * v3.x;
        acc.y += w0 * v0.y + w1 * v1.y + w2 * v2.y + w3 * v3.y;
        acc.z += w0 * v0.z + w1 * v1.z + w2 * v2.z + w3 * v3.z;
        acc.w += w0 * v0.w + w1 * v1.w + w2 * v2.w + w3 * v3.w;
    }
    for (; j < end; j++) {
        int s = csrc[j];
        float w = dinv[s];
        float4 v = reinterpret_cast<const float4*>(h + (size_t)s * 128)[lane];
        acc.x += w * v.x; acc.y += w * v.y; acc.z += w * v.z; acc.w += w * v.w;
    }
    acc.x *= dd; acc.y *= dd; acc.z *= dd; acc.w *= dd;

    if (FINAL) {
        float a = *ap;
        float4 bb = reinterpret_cast<const float4*>(bias)[lane];
        acc.x += bb.x; acc.y += bb.y; acc.z += bb.z; acc.w += bb.w;
        acc.x = acc.x >= 0.f ? acc.x : a * acc.x;
        acc.y = acc.y >= 0.f ? acc.y : a * acc.y;
        acc.z = acc.z >= 0.f ? acc.z : a * acc.z;
        acc.w = acc.w >= 0.f ? acc.w : a * acc.w;
        reinterpret_cast<float4*>(out2 + (size_t)d * 128)[lane] = acc;
    }
    reinterpret_cast<float4*>(out + (size_t)d * 128)[lane] = acc;
}

// ---------------- tf32 tensor-core GEMM: C = epi(A @ B) ----------------
__device__ __forceinline__ uint32_t f2tf32(float f) {
    uint32_t u;
    asm("cvt.rna.tf32.f32 %0, %1;" : "=r"(u) : "f"(f));
    return u;
}

__device__ __forceinline__ void mma_tf32(float* c, const uint32_t* a, const uint32_t* b) {
    asm volatile(
        "mma.sync.aligned.m16n8k8.row.col.f32.tf32.tf32.f32 "
        "{%0,%1,%2,%3}, {%4,%5,%6,%7}, {%8,%9}, {%0,%1,%2,%3};"
        : "+f"(c[0]), "+f"(c[1]), "+f"(c[2]), "+f"(c[3])
        : "r"(a[0]), "r"(a[1]), "r"(a[2]), "r"(a[3]),
          "r"(b[0]), "r"(b[1]));
}

// EPI: 0 raw  1 prelu(acc+bias)  2 relu(acc+bias)  3 acc+bias
template <int EPI>
__global__ __launch_bounds__(256) void tgemm128(
    int M, int N, int K,
    const float* __restrict__ A, const float* __restrict__ B,
    const float* __restrict__ bias, const float* __restrict__ prelu_a,
    float* __restrict__ C)
{
    constexpr int BK = 16;
    constexpr int LDSM = 136;
    __shared__ uint32_t As[BK * LDSM];   // [k][m]
    __shared__ uint32_t Bs[BK * LDSM];   // [k][n]

    const int tid  = threadIdx.x;
    const int lane = tid & 31;
    const int wid  = tid >> 5;
    const int g    = lane >> 2;
    const int t    = lane & 3;

    const int warpM = (wid & 1) * 64;
    const int warpN = (wid >> 1) * 32;

    const int gRow = blockIdx.y * 128;
    const int gCol = blockIdx.x * 128;

    float c[4][4][4];
#pragma unroll
    for (int mt = 0; mt < 4; mt++)
#pragma unroll
        for (int nt = 0; nt < 4; nt++)
#pragma unroll
            for (int i = 0; i < 4; i++) c[mt][nt][i] = 0.f;

    float4 avr[2], bvr[2];

    auto loadA = [&](int k0, float4* r) {
#pragma unroll
        for (int i = 0; i < 2; i++) {
            int idx = tid + i * 256;
            int m = idx >> 2, kq = (idx & 3) << 2;
            int gm = gRow + m;
            r[i] = (gm < M)
                 ? *reinterpret_cast<const float4*>(&A[(size_t)gm * K + k0 + kq])
                 : make_float4(0.f, 0.f, 0.f, 0.f);
        }
    };
    auto loadB = [&](int k0, float4* r) {
#pragma unroll
        for (int i = 0; i < 2; i++) {
            int idx = tid + i * 256;
            int k = idx >> 5, n4 = (idx & 31) << 2;
            r[i] = *reinterpret_cast<const float4*>(&B[(size_t)(k0 + k) * N + gCol + n4]);
        }
    };
    auto stageA = [&](const float4* r) {
#pragma unroll
        for (int i = 0; i < 2; i++) {
            int idx = tid + i * 256;
            int m = idx >> 2, kq = (idx & 3) << 2;
            As[(kq + 0) * LDSM + m] = f2tf32(r[i].x);
            As[(kq + 1) * LDSM + m] = f2tf32(r[i].y);
            As[(kq + 2) * LDSM + m] = f2tf32(r[i].z);
            As[(kq + 3) * LDSM + m] = f2tf32(r[i].w);
        }
    };
    auto stageB = [&](const float4* r) {
#pragma unroll
        for (int i = 0; i < 2; i++) {
            int idx = tid + i * 256;
            int k = idx >> 5, n4 = (idx & 31) << 2;
            uint4 u = make_uint4(f2tf32(r[i].x), f2tf32(r[i].y),
                                 f2tf32(r[i].z), f2tf32(r[i].w));
            *reinterpret_cast<uint4*>(&Bs[k * LDSM + n4]) = u;
        }
    };

    loadA(0, avr); loadB(0, bvr);

    for (int k0 = 0; k0 < K; k0 += BK) {
        stageA(avr); stageB(bvr);
        __syncthreads();
        if (k0 + BK < K) { loadA(k0 + BK, avr); loadB(k0 + BK, bvr); }

#pragma unroll
        for (int kk = 0; kk < BK; kk += 8) {
            uint32_t af[4][4], bf[4][2];
#pragma unroll
            for (int mt = 0; mt < 4; mt++) {
                int m0 = warpM + mt * 16 + g;
                af[mt][0] = As[(kk + t    ) * LDSM + m0];
                af[mt][1] = As[(kk + t    ) * LDSM + m0 + 8];
                af[mt][2] = As[(kk + t + 4) * LDSM + m0];
                af[mt][3] = As[(kk + t + 4) * LDSM + m0 + 8];
            }
#pragma unroll
            for (int nt = 0; nt < 4; nt++) {
                int n0 = warpN + nt * 8 + g;
                bf[nt][0] = Bs[(kk + t    ) * LDSM + n0];
                bf[nt][1] = Bs[(kk + t + 4) * LDSM + n0];
            }
#pragma unroll
            for (int mt = 0; mt < 4; mt++)
#pragma unroll
                for (int nt = 0; nt < 4; nt++)
                    mma_tf32(c[mt][nt], af[mt], bf[nt]);
        }
        __syncthreads();
    }

    float a_val = 0.f;
    if (EPI == 1) a_val = *prelu_a;

#pragma unroll
    for (int mt = 0; mt < 4; mt++) {
        int r0 = gRow + warpM + mt * 16 + g;
        int r1 = r0 + 8;
#pragma unroll
        for (int nt = 0; nt < 4; nt++) {
            int col = gCol + warpN + nt * 8 + t * 2;
            float v0 = c[mt][nt][0], v1 = c[mt][nt][1];
            float v2 = c[mt][nt][2], v3 = c[mt][nt][3];

            if (EPI == 1 || EPI == 2 || EPI == 3) {
                float b0 = bias[col], b1 = bias[col + 1];
                v0 += b0; v1 += b1; v2 += b0; v3 += b1;
            }
            if (EPI == 1) {
                v0 = v0 >= 0.f ? v0 : a_val * v0;
                v1 = v1 >= 0.f ? v1 : a_val * v1;
                v2 = v2 >= 0.f ? v2 : a_val * v2;
                v3 = v3 >= 0.f ? v3 : a_val * v3;
            }
            if (EPI == 2) {
                v0 = fmaxf(v0, 0.f); v1 = fmaxf(v1, 0.f);
                v2 = fmaxf(v2, 0.f); v3 = fmaxf(v3, 0.f);
            }

            if (r0 < M)
                *reinterpret_cast<float2*>(&C[(size_t)r0 * N + col]) = make_float2(v0, v1);
            if (r1 < M)
                *reinterpret_cast<float2*>(&C[(size_t)r1 * N + col]) = make_float2(v2, v3);
        }
    }
}

// ---------------- launch ----------------
extern "C" void kernel_launch(void* const* d_in, const int* in_sizes, int n_in,
                              void* d_out, int out_size) {
    const float* x    = (const float*)d_in[0];
    const int*   ei   = (const int*)d_in[1];
    const float* W1   = (const float*)d_in[2];
    const float* b1   = (const float*)d_in[3];
    const float* W2   = (const float*)d_in[4];
    const float* b2   = (const float*)d_in[5];
    const float* a    = (const float*)d_in[6];
    const float* fc1w = (const float*)d_in[7];
    const float* fc1b = (const float*)d_in[8];
    const float* fc2w = (const float*)d_in[9];
    const float* fc2b = (const float*)d_in[10];

    const int N = in_sizes[0] / 128;      // 100000 nodes
    const int E = in_sizes[1] / 2;        // 1600000 edges
    const int* src = ei;
    const int* dst = ei + E;

    float* out  = (float*)d_out;                    // [N,128]
    float* proj = out + (size_t)N * 128;            // [N,128]

    float *pd, *pagg, *pout1, *ph2;
    int *pdeg, *pexcl, *pbtot, *prowp, *pcur, *pcsrc;
    cudaGetSymbolAddress((void**)&pd,    g_dinv);
    cudaGetSymbolAddress((void**)&pagg,  g_agg);
    cudaGetSymbolAddress((void**)&pout1, g_out1);
    cudaGetSymbolAddress((void**)&ph2,   g_h2);
    cudaGetSymbolAddress((void**)&pdeg,  g_deg);
    cudaGetSymbolAddress((void**)&pexcl, g_excl);
    cudaGetSymbolAddress((void**)&pbtot, g_btot);
    cudaGetSymbolAddress((void**)&prowp, g_rowp);
    cudaGetSymbolAddress((void**)&pcur,  g_cur);
    cudaGetSymbolAddress((void**)&pcsrc, g_csrc);

    const int TPB = 256;
    const int nb  = (N + SCAN_B - 1) / SCAN_B;
    const int aggBlocks = (N * 32 + TPB - 1) / TPB;

    // ---- CSR build ----
    cudaMemsetAsync(pdeg, 0, N * sizeof(int));
    k_hist<<<(E + TPB - 1) / TPB, TPB>>>(dst, pdeg, E);
    k_scan_blocks<<<nb, SCAN_B>>>(pdeg, pexcl, pbtot, N);
    k_scan_tops<<<1, 128>>>(pbtot, nb);
    k_finalize<<<(N + TPB - 1) / TPB, TPB>>>(pdeg, pexcl, pbtot, prowp, pcur, pd, N);
    k_fillcsr<<<(E + TPB - 1) / TPB, TPB>>>(src, dst, pcur, pcsrc, E);

    // ---- layer 1: agg_x = A_hat @ x ; out1 = prelu(agg_x @ W1 + b1) ----
    k_agg<false><<<aggBlocks, TPB>>>(prowp, pcsrc, pd, x, pagg,
                                     nullptr, nullptr, nullptr, N);
    dim3 grid1(2, (N + 127) / 128);
    dim3 grid2(1, (N + 127) / 128);
    tgemm128<1><<<grid1, 256>>>(N, 256, 128, pagg, W1, b1, a, pout1);

    // ---- layer 2: h2 = out1 @ W2 ; out = prelu(A_hat @ h2 + b2) ----
    tgemm128<0><<<grid2, 256>>>(N, 128, 256, pout1, W2, nullptr, nullptr, ph2);
    k_agg<true><<<aggBlocks, TPB>>>(prowp, pcsrc, pd, ph2, pagg,
                                    b2, a, out, N);

    // ---- proj head ----
    tgemm128<2><<<grid2, 256>>>(N, 128, 128, pagg, fc1w, fc1b, nullptr, pout1);
    tgemm128<3><<<grid2, 256>>>(N, 128, 128, pout1, fc2w, fc2b, nullptr, proj);
}

// round 9
// speedup vs baseline: 4.3213x; 1.0787x over previous
#include <cuda_runtime.h>
#include <cstdint>

// ---------------- static scratch (no allocations allowed) ----------------
#define MAXN 100000
#define MAXE 1600000
#define SCAN_B 1024

__device__ float g_dinv[MAXN];
__device__ float g_agg [MAXN * 128];      // agg_x -> layer2 result copy
__device__ float g_out1[MAXN * 256];      // layer-1 output; later proj hidden
__device__ float g_h2  [MAXN * 128];      // out1 @ W2 (pre-aggregation)
__device__ int   g_deg [MAXN];
__device__ int   g_excl[MAXN];
__device__ int   g_btot[128];
__device__ int   g_rowp[MAXN + 1];
__device__ int   g_cur [MAXN];
__device__ int   g_csrc[MAXE];

// ---------------- CSR build ----------------
__global__ void k_hist(const int* __restrict__ dst, int* deg, int E) {
    int e = blockIdx.x * blockDim.x + threadIdx.x;
    if (e < E) atomicAdd(&deg[dst[e]], 1);
}

__global__ void k_scan_blocks(const int* __restrict__ deg, int* excl,
                              int* btot, int n) {
    __shared__ int sh[SCAN_B];
    int t = threadIdx.x;
    int i = blockIdx.x * SCAN_B + t;
    int v = (i < n) ? deg[i] : 0;
    sh[t] = v;
    __syncthreads();
    for (int off = 1; off < SCAN_B; off <<= 1) {
        int add = (t >= off) ? sh[t - off] : 0;
        __syncthreads();
        sh[t] += add;
        __syncthreads();
    }
    if (i < n) excl[i] = sh[t] - v;
    if (t == SCAN_B - 1) btot[blockIdx.x] = sh[t];
}

__global__ void k_scan_tops(int* btot, int nb) {   // 1 block, 128 threads
    __shared__ int sh[128];
    int t = threadIdx.x;
    int v = (t < nb) ? btot[t] : 0;
    sh[t] = v;
    __syncthreads();
    for (int off = 1; off < 128; off <<= 1) {
        int add = (t >= off) ? sh[t - off] : 0;
        __syncthreads();
        sh[t] += add;
        __syncthreads();
    }
    if (t < nb) btot[t] = sh[t] - v;
}

__global__ void k_finalize(const int* __restrict__ deg, const int* __restrict__ excl,
                           const int* __restrict__ btot,
                           int* rowp, int* cur, float* dinv, int n) {
    int i = blockIdx.x * blockDim.x + threadIdx.x;
    if (i >= n) return;
    int rp = excl[i] + btot[i >> 10];
    rowp[i] = rp;
    cur[i]  = rp;
    dinv[i] = rsqrtf((float)deg[i] + 1.0f);   // +1 self-loop
    if (i == n - 1) rowp[n] = rp + deg[i];
}

__global__ void k_fillcsr(const int* __restrict__ src, const int* __restrict__ dst,
                          int* cur, int* csrc, int E) {
    int e = blockIdx.x * blockDim.x + threadIdx.x;
    if (e >= E) return;
    int pos = atomicAdd(&cur[dst[e]], 1);
    csrc[pos] = src[e];
}

// ---------------- CSR aggregation: warp per dst node ----------------
template <bool FINAL>
__global__ void k_agg(const int* __restrict__ rowp, const int* __restrict__ csrc,
                      const float* __restrict__ dinv, const float* __restrict__ h,
                      float* __restrict__ out,
                      const float* __restrict__ bias, const float* __restrict__ ap,
                      float* __restrict__ out2, int n) {
    int gtid = blockIdx.x * blockDim.x + threadIdx.x;
    int d = gtid >> 5, lane = gtid & 31;
    if (d >= n) return;

    float dd = dinv[d];
    float4 acc = reinterpret_cast<const float4*>(h + (size_t)d * 128)[lane];
    acc.x *= dd; acc.y *= dd; acc.z *= dd; acc.w *= dd;

    int j = rowp[d], end = rowp[d + 1];
    for (; j + 4 <= end; j += 4) {
        int s0 = csrc[j], s1 = csrc[j + 1], s2 = csrc[j + 2], s3 = csrc[j + 3];
        float w0 = dinv[s0], w1 = dinv[s1], w2 = dinv[s2], w3 = dinv[s3];
        float4 v0 = reinterpret_cast<const float4*>(h + (size_t)s0 * 128)[lane];
        float4 v1 = reinterpret_cast<const float4*>(h + (size_t)s1 * 128)[lane];
        float4 v2 = reinterpret_cast<const float4*>(h + (size_t)s2 * 128)[lane];
        float4 v3 = reinterpret_cast<const float4*>(h + (size_t)s3 * 128)[lane];
        acc.x += w0 * v0.x + w1 * v1.x + w2 * v2.x + w3 * v3.x;
        acc.y += w0 * v0.y + w1 * v1.y + w2 * v2.y + w3 * v3.y;
        acc.z += w0 * v0.z + w1 * v1.z + w2 * v2.z + w3 * v3.z;
        acc.w += w0 * v0.w + w1 * v1.w + w2 * v2.w + w3 * v3.w;
    }
    for (; j < end; j++) {
        int s = csrc[j];
        float w = dinv[s];
        float4 v = reinterpret_cast<const float4*>(h + (size_t)s * 128)[lane];
        acc.x += w * v.x; acc.y += w * v.y; acc.z += w * v.z; acc.w += w * v.w;
    }
    acc.x *= dd; acc.y *= dd; acc.z *= dd; acc.w *= dd;

    if (FINAL) {
        float a = *ap;
        float4 bb = reinterpret_cast<const float4*>(bias)[lane];
        acc.x += bb.x; acc.y += bb.y; acc.z += bb.z; acc.w += bb.w;
        acc.x = acc.x >= 0.f ? acc.x : a * acc.x;
        acc.y = acc.y >= 0.f ? acc.y : a * acc.y;
        acc.z = acc.z >= 0.f ? acc.z : a * acc.z;
        acc.w = acc.w >= 0.f ? acc.w : a * acc.w;
        reinterpret_cast<float4*>(out2 + (size_t)d * 128)[lane] = acc;
    }
    reinterpret_cast<float4*>(out + (size_t)d * 128)[lane] = acc;
}

// ------------- tf32 tensor-core GEMM, cp.async double-buffered -------------
__device__ __forceinline__ uint32_t f2tf32(float f) {
    uint32_t u;
    asm("cvt.rna.tf32.f32 %0, %1;" : "=r"(u) : "f"(f));
    return u;
}

__device__ __forceinline__ void mma_tf32(float* c, const uint32_t* a, const uint32_t* b) {
    asm volatile(
        "mma.sync.aligned.m16n8k8.row.col.f32.tf32.tf32.f32 "
        "{%0,%1,%2,%3}, {%4,%5,%6,%7}, {%8,%9}, {%0,%1,%2,%3};"
        : "+f"(c[0]), "+f"(c[1]), "+f"(c[2]), "+f"(c[3])
        : "r"(a[0]), "r"(a[1]), "r"(a[2]), "r"(a[3]),
          "r"(b[0]), "r"(b[1]));
}

__device__ __forceinline__ void cp16(void* smem_dst, const void* gsrc, bool valid) {
    uint32_t saddr = (uint32_t)__cvta_generic_to_shared(smem_dst);
    int sz = valid ? 16 : 0;
    asm volatile("cp.async.cg.shared.global [%0], [%1], 16, %2;"
                 :: "r"(saddr), "l"(gsrc), "r"(sz));
}
#define CP_COMMIT asm volatile("cp.async.commit_group;")
#define CP_WAIT(n) asm volatile("cp.async.wait_group %0;" :: "n"(n))

// EPI: 0 raw  1 prelu(acc+bias)  2 relu(acc+bias)  3 acc+bias
template <int EPI>
__global__ __launch_bounds__(256) void tgemm128(
    int M, int N, int K,
    const float* __restrict__ A, const float* __restrict__ B,
    const float* __restrict__ bias, const float* __restrict__ prelu_a,
    float* __restrict__ C)
{
    constexpr int BK = 16;
    constexpr int LDSA = 20;    // A stored [m][k], padded (banks (20g+t)%32 distinct)
    constexpr int LDSN = 136;   // B stored [k][n], padded (banks (8t+g)%32 distinct)
    __shared__ float As[2][128 * LDSA];
    __shared__ float Bs[2][BK * LDSN];

    const int tid  = threadIdx.x;
    const int lane = tid & 31;
    const int wid  = tid >> 5;
    const int g    = lane >> 2;
    const int t    = lane & 3;

    const int warpM = (wid & 1) * 64;
    const int warpN = (wid >> 1) * 32;

    const int gRow = blockIdx.y * 128;
    const int gCol = blockIdx.x * 128;

    // per-thread copy coordinates
    const int am  = tid >> 1;                 // with i*128 offset below: 2 chunks
    // A tile: 128 rows x 16 k = 512 x 16B chunks; thread handles idx=tid, tid+256
    // B tile: 16 k x 128 n   = 512 x 16B chunks

    auto issueTile = [&](int k0, int s) {
#pragma unroll
        for (int i = 0; i < 2; i++) {
            int idx = tid + i * 256;
            int m  = idx >> 2, kq = (idx & 3) << 2;
            int gm = gRow + m;
            cp16(&As[s][m * LDSA + kq], &A[(size_t)gm * K + k0 + kq], gm < M);
        }
#pragma unroll
        for (int i = 0; i < 2; i++) {
            int idx = tid + i * 256;
            int k = idx >> 5, n4 = (idx & 31) << 2;
            cp16(&Bs[s][k * LDSN + n4], &B[(size_t)(k0 + k) * N + gCol + n4], true);
        }
    };

    float c[4][4][4];
#pragma unroll
    for (int mt = 0; mt < 4; mt++)
#pragma unroll
        for (int nt = 0; nt < 4; nt++)
#pragma unroll
            for (int i = 0; i < 4; i++) c[mt][nt][i] = 0.f;

    const int T = K / BK;
    issueTile(0, 0);
    CP_COMMIT;

    for (int it = 0; it < T; it++) {
        int s = it & 1;
        if (it + 1 < T) {
            issueTile((it + 1) * BK, s ^ 1);
            CP_COMMIT;
            CP_WAIT(1);
        } else {
            CP_WAIT(0);
        }
        __syncthreads();

#pragma unroll
        for (int kk = 0; kk < BK; kk += 8) {
            uint32_t af[4][4], bf[4][2];
#pragma unroll
            for (int mt = 0; mt < 4; mt++) {
                int m0 = warpM + mt * 16 + g;
                af[mt][0] = f2tf32(As[s][(m0    ) * LDSA + kk + t    ]);
                af[mt][1] = f2tf32(As[s][(m0 + 8) * LDSA + kk + t    ]);
                af[mt][2] = f2tf32(As[s][(m0    ) * LDSA + kk + t + 4]);
                af[mt][3] = f2tf32(As[s][(m0 + 8) * LDSA + kk + t + 4]);
            }
#pragma unroll
            for (int nt = 0; nt < 4; nt++) {
                int n0 = warpN + nt * 8 + g;
                bf[nt][0] = f2tf32(Bs[s][(kk + t    ) * LDSN + n0]);
                bf[nt][1] = f2tf32(Bs[s][(kk + t + 4) * LDSN + n0]);
            }
#pragma unroll
            for (int mt = 0; mt < 4; mt++)
#pragma unroll
                for (int nt = 0; nt < 4; nt++)
                    mma_tf32(c[mt][nt], af[mt], bf[nt]);
        }
        __syncthreads();
    }

    float a_val = 0.f;
    if (EPI == 1) a_val = *prelu_a;

#pragma unroll
    for (int mt = 0; mt < 4; mt++) {
        int r0 = gRow + warpM + mt * 16 + g;
        int r1 = r0 + 8;
#pragma unroll
        for (int nt = 0; nt < 4; nt++) {
            int col = gCol + warpN + nt * 8 + t * 2;
            float v0 = c[mt][nt][0], v1 = c[mt][nt][1];
            float v2 = c[mt][nt][2], v3 = c[mt][nt][3];

            if (EPI == 1 || EPI == 2 || EPI == 3) {
                float b0 = bias[col], b1 = bias[col + 1];
                v0 += b0; v1 += b1; v2 += b0; v3 += b1;
            }
            if (EPI == 1) {
                v0 = v0 >= 0.f ? v0 : a_val * v0;
                v1 = v1 >= 0.f ? v1 : a_val * v1;
                v2 = v2 >= 0.f ? v2 : a_val * v2;
                v3 = v3 >= 0.f ? v3 : a_val * v3;
            }
            if (EPI == 2) {
                v0 = fmaxf(v0, 0.f); v1 = fmaxf(v1, 0.f);
                v2 = fmaxf(v2, 0.f); v3 = fmaxf(v3, 0.f);
            }

            if (r0 < M)
                *reinterpret_cast<float2*>(&C[(size_t)r0 * N + col]) = make_float2(v0, v1);
            if (r1 < M)
                *reinterpret_cast<float2*>(&C[(size_t)r1 * N + col]) = make_float2(v2, v3);
        }
    }
}

// ---------------- launch ----------------
extern "C" void kernel_launch(void* const* d_in, const int* in_sizes, int n_in,
                              void* d_out, int out_size) {
    const float* x    = (const float*)d_in[0];
    const int*   ei   = (const int*)d_in[1];
    const float* W1   = (const float*)d_in[2];
    const float* b1   = (const float*)d_in[3];
    const float* W2   = (const float*)d_in[4];
    const float* b2   = (const float*)d_in[5];
    const float* a    = (const float*)d_in[6];
    const float* fc1w = (const float*)d_in[7];
    const float* fc1b = (const float*)d_in[8];
    const float* fc2w = (const float*)d_in[9];
    const float* fc2b = (const float*)d_in[10];

    const int N = in_sizes[0] / 128;      // 100000 nodes
    const int E = in_sizes[1] / 2;        // 1600000 edges
    const int* src = ei;
    const int* dst = ei + E;

    float* out  = (float*)d_out;                    // [N,128]
    float* proj = out + (size_t)N * 128;            // [N,128]

    float *pd, *pagg, *pout1, *ph2;
    int *pdeg, *pexcl, *pbtot, *prowp, *pcur, *pcsrc;
    cudaGetSymbolAddress((void**)&pd,    g_dinv);
    cudaGetSymbolAddress((void**)&pagg,  g_agg);
    cudaGetSymbolAddress((void**)&pout1, g_out1);
    cudaGetSymbolAddress((void**)&ph2,   g_h2);
    cudaGetSymbolAddress((void**)&pdeg,  g_deg);
    cudaGetSymbolAddress((void**)&pexcl, g_excl);
    cudaGetSymbolAddress((void**)&pbtot, g_btot);
    cudaGetSymbolAddress((void**)&prowp, g_rowp);
    cudaGetSymbolAddress((void**)&pcur,  g_cur);
    cudaGetSymbolAddress((void**)&pcsrc, g_csrc);

    const int TPB = 256;
    const int nb  = (N + SCAN_B - 1) / SCAN_B;
    const int aggBlocks = (N * 32 + TPB - 1) / TPB;

    // ---- CSR build ----
    cudaMemsetAsync(pdeg, 0, N * sizeof(int));
    k_hist<<<(E + TPB - 1) / TPB, TPB>>>(dst, pdeg, E);
    k_scan_blocks<<<nb, SCAN_B>>>(pdeg, pexcl, pbtot, N);
    k_scan_tops<<<1, 128>>>(pbtot, nb);
    k_finalize<<<(N + TPB - 1) / TPB, TPB>>>(pdeg, pexcl, pbtot, prowp, pcur, pd, N);
    k_fillcsr<<<(E + TPB - 1) / TPB, TPB>>>(src, dst, pcur, pcsrc, E);

    // ---- layer 1 ----
    k_agg<false><<<aggBlocks, TPB>>>(prowp, pcsrc, pd, x, pagg,
                                     nullptr, nullptr, nullptr, N);
    dim3 grid1(2, (N + 127) / 128);
    dim3 grid2(1, (N + 127) / 128);
    tgemm128<1><<<grid1, 256>>>(N, 256, 128, pagg, W1, b1, a, pout1);

    // ---- layer 2 ----
    tgemm128<0><<<grid2, 256>>>(N, 128, 256, pout1, W2, nullptr, nullptr, ph2);
    k_agg<true><<<aggBlocks, TPB>>>(prowp, pcsrc, pd, ph2, pagg,
                                    b2, a, out, N);

    // ---- proj head ----
    tgemm128<2><<<grid2, 256>>>(N, 128, 128, pagg, fc1w, fc1b, nullptr, pout1);
    tgemm128<3><<<grid2, 256>>>(N, 128, 128, pout1, fc2w, fc2b, nullptr, proj);
}

// round 10
// speedup vs baseline: 4.3978x; 1.0177x over previous
#include <cuda_runtime.h>
#include <cstdint>

// ---------------- static scratch (no allocations allowed) ----------------
#define MAXN 100000
#define MAXE 1600000
#define SCAN_B 1024

__device__ float g_dinv[MAXN];
__device__ float g_agg [MAXN * 128];      // agg_x -> layer2 result copy
__device__ float g_out1[MAXN * 256];      // layer-1 output
__device__ float g_h2  [MAXN * 128];      // out1 @ W2 (pre-aggregation)
__device__ int   g_deg [MAXN];            // zero at entry; re-zeroed in k_finalize
__device__ int   g_excl[MAXN];
__device__ int   g_btot[128];
__device__ int   g_rowp[MAXN + 1];
__device__ int   g_cur [MAXN];
__device__ int   g_csrc[MAXE];

// ---------------- CSR build ----------------
__global__ void k_hist(const int* __restrict__ dst, int* deg, int E) {
    int e = blockIdx.x * blockDim.x + threadIdx.x;
    if (e < E) atomicAdd(&deg[dst[e]], 1);
}

__global__ void k_scan_blocks(const int* __restrict__ deg, int* excl,
                              int* btot, int n) {
    __shared__ int sh[SCAN_B];
    int t = threadIdx.x;
    int i = blockIdx.x * SCAN_B + t;
    int v = (i < n) ? deg[i] : 0;
    sh[t] = v;
    __syncthreads();
    for (int off = 1; off < SCAN_B; off <<= 1) {
        int add = (t >= off) ? sh[t - off] : 0;
        __syncthreads();
        sh[t] += add;
        __syncthreads();
    }
    if (i < n) excl[i] = sh[t] - v;
    if (t == SCAN_B - 1) btot[blockIdx.x] = sh[t];
}

__global__ void k_scan_tops(int* btot, int nb) {   // 1 block, 128 threads
    __shared__ int sh[128];
    int t = threadIdx.x;
    int v = (t < nb) ? btot[t] : 0;
    sh[t] = v;
    __syncthreads();
    for (int off = 1; off < 128; off <<= 1) {
        int add = (t >= off) ? sh[t - off] : 0;
        __syncthreads();
        sh[t] += add;
        __syncthreads();
    }
    if (t < nb) btot[t] = sh[t] - v;
}

// rowp/cur/dinv; re-zeroes deg for the next replay (globals are 0 at load).
__global__ void k_finalize(int* deg, const int* __restrict__ excl,
                           const int* __restrict__ btot,
                           int* rowp, int* cur, float* dinv, int n) {
    int i = blockIdx.x * blockDim.x + threadIdx.x;
    if (i >= n) return;
    int dg = deg[i];
    int rp = excl[i] + btot[i >> 10];
    rowp[i] = rp;
    cur[i]  = rp;
    dinv[i] = rsqrtf((float)dg + 1.0f);   // +1 self-loop
    if (i == n - 1) rowp[n] = rp + dg;
    deg[i] = 0;                            // ready for next launch/replay
}

__global__ void k_fillcsr(const int* __restrict__ src, const int* __restrict__ dst,
                          int* cur, int* csrc, int E) {
    int e = blockIdx.x * blockDim.x + threadIdx.x;
    if (e >= E) return;
    int pos = atomicAdd(&cur[dst[e]], 1);
    csrc[pos] = src[e];
}

// ---------------- CSR aggregation: warp per dst node ----------------
template <bool FINAL>
__global__ void k_agg(const int* __restrict__ rowp, const int* __restrict__ csrc,
                      const float* __restrict__ dinv, const float* __restrict__ h,
                      float* __restrict__ out,
                      const float* __restrict__ bias, const float* __restrict__ ap,
                      float* __restrict__ out2, int n) {
    int gtid = blockIdx.x * blockDim.x + threadIdx.x;
    int d = gtid >> 5, lane = gtid & 31;
    if (d >= n) return;

    float dd = dinv[d];
    float4 acc = reinterpret_cast<const float4*>(h + (size_t)d * 128)[lane];
    acc.x *= dd; acc.y *= dd; acc.z *= dd; acc.w *= dd;

    int j = rowp[d], end = rowp[d + 1];
    for (; j + 4 <= end; j += 4) {
        int s0 = csrc[j], s1 = csrc[j + 1], s2 = csrc[j + 2], s3 = csrc[j + 3];
        float w0 = dinv[s0], w1 = dinv[s1], w2 = dinv[s2], w3 = dinv[s3];
        float4 v0 = reinterpret_cast<const float4*>(h + (size_t)s0 * 128)[lane];
        float4 v1 = reinterpret_cast<const float4*>(h + (size_t)s1 * 128)[lane];
        float4 v2 = reinterpret_cast<const float4*>(h + (size_t)s2 * 128)[lane];
        float4 v3 = reinterpret_cast<const float4*>(h + (size_t)s3 * 128)[lane];
        acc.x += w0 * v0.x + w1 * v1.x + w2 * v2.x + w3 * v3.x;
        acc.y += w0 * v0.y + w1 * v1.y + w2 * v2.y + w3 * v3.y;
        acc.z += w0 * v0.z + w1 * v1.z + w2 * v2.z + w3 * v3.z;
        acc.w += w0 * v0.w + w1 * v1.w + w2 * v2.w + w3 * v3.w;
    }
    for (; j < end; j++) {
        int s = csrc[j];
        float w = dinv[s];
        float4 v = reinterpret_cast<const float4*>(h + (size_t)s * 128)[lane];
        acc.x += w * v.x; acc.y += w * v.y; acc.z += w * v.z; acc.w += w * v.w;
    }
    acc.x *= dd; acc.y *= dd; acc.z *= dd; acc.w *= dd;

    if (FINAL) {
        float a = *ap;
        float4 bb = reinterpret_cast<const float4*>(bias)[lane];
        acc.x += bb.x; acc.y += bb.y; acc.z += bb.z; acc.w += bb.w;
        acc.x = acc.x >= 0.f ? acc.x : a * acc.x;
        acc.y = acc.y >= 0.f ? acc.y : a * acc.y;
        acc.z = acc.z >= 0.f ? acc.z : a * acc.z;
        acc.w = acc.w >= 0.f ? acc.w : a * acc.w;
        reinterpret_cast<float4*>(out2 + (size_t)d * 128)[lane] = acc;
    }
    reinterpret_cast<float4*>(out + (size_t)d * 128)[lane] = acc;
}

// ------------- tf32 tensor-core GEMM, cp.async double-buffered -------------
__device__ __forceinline__ uint32_t f2tf32(float f) {
    uint32_t u;
    asm("cvt.rna.tf32.f32 %0, %1;" : "=r"(u) : "f"(f));
    return u;
}

__device__ __forceinline__ void mma_tf32(float* c, const uint32_t* a, const uint32_t* b) {
    asm volatile(
        "mma.sync.aligned.m16n8k8.row.col.f32.tf32.tf32.f32 "
        "{%0,%1,%2,%3}, {%4,%5,%6,%7}, {%8,%9}, {%0,%1,%2,%3};"
        : "+f"(c[0]), "+f"(c[1]), "+f"(c[2]), "+f"(c[3])
        : "r"(a[0]), "r"(a[1]), "r"(a[2]), "r"(a[3]),
          "r"(b[0]), "r"(b[1]));
}

__device__ __forceinline__ void cp16(void* smem_dst, const void* gsrc, bool valid) {
    uint32_t saddr = (uint32_t)__cvta_generic_to_shared(smem_dst);
    int sz = valid ? 16 : 0;
    asm volatile("cp.async.cg.shared.global [%0], [%1], 16, %2;"
                 :: "r"(saddr), "l"(gsrc), "r"(sz));
}
#define CP_COMMIT asm volatile("cp.async.commit_group;")
#define CP_WAIT(n) asm volatile("cp.async.wait_group %0;" :: "n"(n))

// EPI: 0 raw  1 prelu(acc+bias)  2 relu(acc+bias)  3 acc+bias
template <int EPI>
__global__ __launch_bounds__(256) void tgemm128(
    int M, int N, int K,
    const float* __restrict__ A, const float* __restrict__ B,
    const float* __restrict__ bias, const float* __restrict__ prelu_a,
    float* __restrict__ C)
{
    constexpr int BK = 16;
    constexpr int LDSA = 20;
    constexpr int LDSN = 136;
    __shared__ float As[2][128 * LDSA];
    __shared__ float Bs[2][BK * LDSN];

    const int tid  = threadIdx.x;
    const int lane = tid & 31;
    const int wid  = tid >> 5;
    const int g    = lane >> 2;
    const int t    = lane & 3;

    const int warpM = (wid & 1) * 64;
    const int warpN = (wid >> 1) * 32;

    const int gRow = blockIdx.y * 128;
    const int gCol = blockIdx.x * 128;

    auto issueTile = [&](int k0, int s) {
#pragma unroll
        for (int i = 0; i < 2; i++) {
            int idx = tid + i * 256;
            int m  = idx >> 2, kq = (idx & 3) << 2;
            int gm = gRow + m;
            cp16(&As[s][m * LDSA + kq], &A[(size_t)gm * K + k0 + kq], gm < M);
        }
#pragma unroll
        for (int i = 0; i < 2; i++) {
            int idx = tid + i * 256;
            int k = idx >> 5, n4 = (idx & 31) << 2;
            cp16(&Bs[s][k * LDSN + n4], &B[(size_t)(k0 + k) * N + gCol + n4], true);
        }
    };

    float c[4][4][4];
#pragma unroll
    for (int mt = 0; mt < 4; mt++)
#pragma unroll
        for (int nt = 0; nt < 4; nt++)
#pragma unroll
            for (int i = 0; i < 4; i++) c[mt][nt][i] = 0.f;

    const int T = K / BK;
    issueTile(0, 0);
    CP_COMMIT;

    for (int it = 0; it < T; it++) {
        int s = it & 1;
        if (it + 1 < T) {
            issueTile((it + 1) * BK, s ^ 1);
            CP_COMMIT;
            CP_WAIT(1);
        } else {
            CP_WAIT(0);
        }
        __syncthreads();

#pragma unroll
        for (int kk = 0; kk < BK; kk += 8) {
            uint32_t af[4][4], bf[4][2];
#pragma unroll
            for (int mt = 0; mt < 4; mt++) {
                int m0 = warpM + mt * 16 + g;
                af[mt][0] = f2tf32(As[s][(m0    ) * LDSA + kk + t    ]);
                af[mt][1] = f2tf32(As[s][(m0 + 8) * LDSA + kk + t    ]);
                af[mt][2] = f2tf32(As[s][(m0    ) * LDSA + kk + t + 4]);
                af[mt][3] = f2tf32(As[s][(m0 + 8) * LDSA + kk + t + 4]);
            }
#pragma unroll
            for (int nt = 0; nt < 4; nt++) {
                int n0 = warpN + nt * 8 + g;
                bf[nt][0] = f2tf32(Bs[s][(kk + t    ) * LDSN + n0]);
                bf[nt][1] = f2tf32(Bs[s][(kk + t + 4) * LDSN + n0]);
            }
#pragma unroll
            for (int mt = 0; mt < 4; mt++)
#pragma unroll
                for (int nt = 0; nt < 4; nt++)
                    mma_tf32(c[mt][nt], af[mt], bf[nt]);
        }
        __syncthreads();
    }

    float a_val = 0.f;
    if (EPI == 1) a_val = *prelu_a;

#pragma unroll
    for (int mt = 0; mt < 4; mt++) {
        int r0 = gRow + warpM + mt * 16 + g;
        int r1 = r0 + 8;
#pragma unroll
        for (int nt = 0; nt < 4; nt++) {
            int col = gCol + warpN + nt * 8 + t * 2;
            float v0 = c[mt][nt][0], v1 = c[mt][nt][1];
            float v2 = c[mt][nt][2], v3 = c[mt][nt][3];

            if (EPI == 1 || EPI == 2 || EPI == 3) {
                float b0 = bias[col], b1 = bias[col + 1];
                v0 += b0; v1 += b1; v2 += b0; v3 += b1;
            }
            if (EPI == 1) {
                v0 = v0 >= 0.f ? v0 : a_val * v0;
                v1 = v1 >= 0.f ? v1 : a_val * v1;
                v2 = v2 >= 0.f ? v2 : a_val * v2;
                v3 = v3 >= 0.f ? v3 : a_val * v3;
            }
            if (EPI == 2) {
                v0 = fmaxf(v0, 0.f); v1 = fmaxf(v1, 0.f);
                v2 = fmaxf(v2, 0.f); v3 = fmaxf(v3, 0.f);
            }

            if (r0 < M)
                *reinterpret_cast<float2*>(&C[(size_t)r0 * N + col]) = make_float2(v0, v1);
            if (r1 < M)
                *reinterpret_cast<float2*>(&C[(size_t)r1 * N + col]) = make_float2(v2, v3);
        }
    }
}

// ---- fused proj head: proj = relu(A@fc1 + b1h) @ fc2 + b2h, hidden in smem ----
// Dynamic smem: As(2*128*20) + Bs(2*16*136) + H(128*132) floats.
__global__ __launch_bounds__(256) void k_proj(
    int M,
    const float* __restrict__ A,
    const float* __restrict__ fc1w, const float* __restrict__ fc1b,
    const float* __restrict__ fc2w, const float* __restrict__ fc2b,
    float* __restrict__ C)
{
    constexpr int BK = 16, LDSA = 20, LDSN = 136, LDH = 132, K = 128, N = 128;
    extern __shared__ float sm[];
    float* As = sm;                      // 2 * 128*20  = 5120
    float* Bs = As + 2 * 128 * LDSA;     // 2 * 16*136  = 4352
    float* H  = Bs + 2 * BK * LDSN;      // 128*132     = 16896

    const int tid  = threadIdx.x;
    const int lane = tid & 31;
    const int wid  = tid >> 5;
    const int g    = lane >> 2;
    const int t    = lane & 3;
    const int warpM = (wid & 1) * 64;
    const int warpN = (wid >> 1) * 32;
    const int gRow = blockIdx.y * 128;

    auto issueA = [&](int k0, int s) {
#pragma unroll
        for (int i = 0; i < 2; i++) {
            int idx = tid + i * 256;
            int m = idx >> 2, kq = (idx & 3) << 2;
            int gm = gRow + m;
            cp16(&As[s * 128 * LDSA + m * LDSA + kq], &A[(size_t)gm * K + k0 + kq], gm < M);
        }
    };
    auto issueB = [&](const float* B, int k0, int s) {
#pragma unroll
        for (int i = 0; i < 2; i++) {
            int idx = tid + i * 256;
            int k = idx >> 5, n4 = (idx & 31) << 2;
            cp16(&Bs[s * BK * LDSN + k * LDSN + n4], &B[(size_t)(k0 + k) * N + n4], true);
        }
    };

    float c[4][4][4];
    auto zeroC = [&]() {
#pragma unroll
        for (int mt = 0; mt < 4; mt++)
#pragma unroll
            for (int nt = 0; nt < 4; nt++)
#pragma unroll
                for (int i = 0; i < 4; i++) c[mt][nt][i] = 0.f;
    };

    // ================= stage 1: H = relu(A @ fc1 + fc1b) =================
    zeroC();
    issueA(0, 0); issueB(fc1w, 0, 0);
    CP_COMMIT;
    const int T = K / BK;
    for (int it = 0; it < T; it++) {
        int s = it & 1;
        if (it + 1 < T) {
            issueA((it + 1) * BK, s ^ 1); issueB(fc1w, (it + 1) * BK, s ^ 1);
            CP_COMMIT; CP_WAIT(1);
        } else CP_WAIT(0);
        __syncthreads();
#pragma unroll
        for (int kk = 0; kk < BK; kk += 8) {
            uint32_t af[4][4], bf[4][2];
#pragma unroll
            for (int mt = 0; mt < 4; mt++) {
                int m0 = warpM + mt * 16 + g;
                const float* Ab = &As[s * 128 * LDSA];
                af[mt][0] = f2tf32(Ab[(m0    ) * LDSA + kk + t    ]);
                af[mt][1] = f2tf32(Ab[(m0 + 8) * LDSA + kk + t    ]);
                af[mt][2] = f2tf32(Ab[(m0    ) * LDSA + kk + t + 4]);
                af[mt][3] = f2tf32(Ab[(m0 + 8) * LDSA + kk + t + 4]);
            }
#pragma unroll
            for (int nt = 0; nt < 4; nt++) {
                int n0 = warpN + nt * 8 + g;
                const float* Bb = &Bs[s * BK * LDSN];
                bf[nt][0] = f2tf32(Bb[(kk + t    ) * LDSN + n0]);
                bf[nt][1] = f2tf32(Bb[(kk + t + 4) * LDSN + n0]);
            }
#pragma unroll
            for (int mt = 0; mt < 4; mt++)
#pragma unroll
                for (int nt = 0; nt < 4; nt++)
                    mma_tf32(c[mt][nt], af[mt], bf[nt]);
        }
        __syncthreads();
    }
    // relu + bias -> H  (H[m][k] stride 132)
#pragma unroll
    for (int mt = 0; mt < 4; mt++) {
        int m0 = warpM + mt * 16 + g;
#pragma unroll
        for (int nt = 0; nt < 4; nt++) {
            int col = warpN + nt * 8 + t * 2;
            float b0 = fc1b[col], b1 = fc1b[col + 1];
            float v0 = fmaxf(c[mt][nt][0] + b0, 0.f);
            float v1 = fmaxf(c[mt][nt][1] + b1, 0.f);
            float v2 = fmaxf(c[mt][nt][2] + b0, 0.f);
            float v3 = fmaxf(c[mt][nt][3] + b1, 0.f);
            *reinterpret_cast<float2*>(&H[(m0    ) * LDH + col]) = make_float2(v0, v1);
            *reinterpret_cast<float2*>(&H[(m0 + 8) * LDH + col]) = make_float2(v2, v3);
        }
    }
    __syncthreads();

    // ================= stage 2: C = H @ fc2 + fc2b =================
    zeroC();
    issueB(fc2w, 0, 0);
    CP_COMMIT;
    for (int it = 0; it < T; it++) {
        int s = it & 1;
        if (it + 1 < T) {
            issueB(fc2w, (it + 1) * BK, s ^ 1);
            CP_COMMIT; CP_WAIT(1);
        } else CP_WAIT(0);
        __syncthreads();
        int kbase = it * BK;
#pragma unroll
        for (int kk = 0; kk < BK; kk += 8) {
            uint32_t af[4][4], bf[4][2];
#pragma unroll
            for (int mt = 0; mt < 4; mt++) {
                int m0 = warpM + mt * 16 + g;
                af[mt][0] = f2tf32(H[(m0    ) * LDH + kbase + kk + t    ]);
                af[mt][1] = f2tf32(H[(m0 + 8) * LDH + kbase + kk + t    ]);
                af[mt][2] = f2tf32(H[(m0    ) * LDH + kbase + kk + t + 4]);
                af[mt][3] = f2tf32(H[(m0 + 8) * LDH + kbase + kk + t + 4]);
            }
#pragma unroll
            for (int nt = 0; nt < 4; nt++) {
                int n0 = warpN + nt * 8 + g;
                const float* Bb = &Bs[s * BK * LDSN];
                bf[nt][0] = f2tf32(Bb[(kk + t    ) * LDSN + n0]);
                bf[nt][1] = f2tf32(Bb[(kk + t + 4) * LDSN + n0]);
            }
#pragma unroll
            for (int mt = 0; mt < 4; mt++)
#pragma unroll
                for (int nt = 0; nt < 4; nt++)
                    mma_tf32(c[mt][nt], af[mt], bf[nt]);
        }
        __syncthreads();
    }
#pragma unroll
    for (int mt = 0; mt < 4; mt++) {
        int r0 = gRow + warpM + mt * 16 + g;
        int r1 = r0 + 8;
#pragma unroll
        for (int nt = 0; nt < 4; nt++) {
            int col = warpN + nt * 8 + t * 2;
            float b0 = fc2b[col], b1 = fc2b[col + 1];
            if (r0 < M)
                *reinterpret_cast<float2*>(&C[(size_t)r0 * N + col]) =
                    make_float2(c[mt][nt][0] + b0, c[mt][nt][1] + b1);
            if (r1 < M)
                *reinterpret_cast<float2*>(&C[(size_t)r1 * N + col]) =
                    make_float2(c[mt][nt][2] + b0, c[mt][nt][3] + b1);
        }
    }
}

// ---------------- launch ----------------
extern "C" void kernel_launch(void* const* d_in, const int* in_sizes, int n_in,
                              void* d_out, int out_size) {
    const float* x    = (const float*)d_in[0];
    const int*   ei   = (const int*)d_in[1];
    const float* W1   = (const float*)d_in[2];
    const float* b1   = (const float*)d_in[3];
    const float* W2   = (const float*)d_in[4];
    const float* b2   = (const float*)d_in[5];
    const float* a    = (const float*)d_in[6];
    const float* fc1w = (const float*)d_in[7];
    const float* fc1b = (const float*)d_in[8];
    const float* fc2w = (const float*)d_in[9];
    const float* fc2b = (const float*)d_in[10];

    const int N = in_sizes[0] / 128;      // 100000 nodes
    const int E = in_sizes[1] / 2;        // 1600000 edges
    const int* src = ei;
    const int* dst = ei + E;

    float* out  = (float*)d_out;                    // [N,128]
    float* proj = out + (size_t)N * 128;            // [N,128]

    float *pd, *pagg, *pout1, *ph2;
    int *pdeg, *pexcl, *pbtot, *prowp, *pcur, *pcsrc;
    cudaGetSymbolAddress((void**)&pd,    g_dinv);
    cudaGetSymbolAddress((void**)&pagg,  g_agg);
    cudaGetSymbolAddress((void**)&pout1, g_out1);
    cudaGetSymbolAddress((void**)&ph2,   g_h2);
    cudaGetSymbolAddress((void**)&pdeg,  g_deg);
    cudaGetSymbolAddress((void**)&pexcl, g_excl);
    cudaGetSymbolAddress((void**)&pbtot, g_btot);
    cudaGetSymbolAddress((void**)&prowp, g_rowp);
    cudaGetSymbolAddress((void**)&pcur,  g_cur);
    cudaGetSymbolAddress((void**)&pcsrc, g_csrc);

    const int TPB = 256;
    const int nb  = (N + SCAN_B - 1) / SCAN_B;
    const int aggBlocks = (N * 32 + TPB - 1) / TPB;
    const int projSmem = (2 * 128 * 20 + 2 * 16 * 136 + 128 * 132) * 4;

    cudaFuncSetAttribute(k_proj, cudaFuncAttributeMaxDynamicSharedMemorySize, projSmem);

    // ---- CSR build (deg enters zeroed: load-time init / re-zeroed below) ----
    k_hist<<<(E + TPB - 1) / TPB, TPB>>>(dst, pdeg, E);
    k_scan_blocks<<<nb, SCAN_B>>>(pdeg, pexcl, pbtot, N);
    k_scan_tops<<<1, 128>>>(pbtot, nb);
    k_finalize<<<(N + TPB - 1) / TPB, TPB>>>(pdeg, pexcl, pbtot, prowp, pcur, pd, N);
    k_fillcsr<<<(E + TPB - 1) / TPB, TPB>>>(src, dst, pcur, pcsrc, E);

    // ---- layer 1 ----
    k_agg<false><<<aggBlocks, TPB>>>(prowp, pcsrc, pd, x, pagg,
                                     nullptr, nullptr, nullptr, N);
    dim3 grid1(2, (N + 127) / 128);
    dim3 grid2(1, (N + 127) / 128);
    tgemm128<1><<<grid1, 256>>>(N, 256, 128, pagg, W1, b1, a, pout1);

    // ---- layer 2 ----
    tgemm128<0><<<grid2, 256>>>(N, 128, 256, pout1, W2, nullptr, nullptr, ph2);
    k_agg<true><<<aggBlocks, TPB>>>(prowp, pcsrc, pd, ph2, pagg,
                                    b2, a, out, N);

    // ---- fused proj head ----
    k_proj<<<grid2, 256, projSmem>>>(N, pagg, fc1w, fc1b, fc2w, fc2b, proj);
}

// round 11
// speedup vs baseline: 4.5312x; 1.0303x over previous
#include <cuda_runtime.h>
#include <cuda_fp16.h>
#include <cstdint>

// ---------------- static scratch (no allocations allowed) ----------------
#define MAXN 100000
#define MAXE 1600000
#define SCAN_B 1024

__device__ float  g_dinv[MAXN];
__device__ float  g_agg [MAXN * 128];     // agg results (fp32)
__device__ float  g_out1[MAXN * 256];     // layer-1 output
__device__ __half g_h16 [MAXN * 128];     // fp16 gather buffer: x, then h2
__device__ int    g_deg [MAXN];           // zero at entry; re-zeroed in k_finalize
__device__ int    g_excl[MAXN];
__device__ int    g_btot[128];
__device__ int    g_rowp[MAXN + 1];
__device__ int    g_cur [MAXN];
__device__ int    g_csrc[MAXE];

// ---------------- fp16 helpers ----------------
__device__ __forceinline__ float4 h4tof4(uint2 r) {
    __half2 p0 = *reinterpret_cast<__half2*>(&r.x);
    __half2 p1 = *reinterpret_cast<__half2*>(&r.y);
    float2 f0 = __half22float2(p0);
    float2 f1 = __half22float2(p1);
    return make_float4(f0.x, f0.y, f1.x, f1.y);
}

// x [n4 float4] -> fp16
__global__ void k_f2h(const float* __restrict__ x, __half* __restrict__ xh, int n4) {
    int i = blockIdx.x * blockDim.x + threadIdx.x;
    if (i >= n4) return;
    float4 v = reinterpret_cast<const float4*>(x)[i];
    __half2 p0 = __floats2half2_rn(v.x, v.y);
    __half2 p1 = __floats2half2_rn(v.z, v.w);
    uint2 r;
    r.x = *reinterpret_cast<uint32_t*>(&p0);
    r.y = *reinterpret_cast<uint32_t*>(&p1);
    reinterpret_cast<uint2*>(xh)[i] = r;
}

// ---------------- CSR build ----------------
__global__ void k_hist(const int* __restrict__ dst, int* deg, int E) {
    int e = blockIdx.x * blockDim.x + threadIdx.x;
    if (e < E) atomicAdd(&deg[dst[e]], 1);
}

__global__ void k_scan_blocks(const int* __restrict__ deg, int* excl,
                              int* btot, int n) {
    __shared__ int sh[SCAN_B];
    int t = threadIdx.x;
    int i = blockIdx.x * SCAN_B + t;
    int v = (i < n) ? deg[i] : 0;
    sh[t] = v;
    __syncthreads();
    for (int off = 1; off < SCAN_B; off <<= 1) {
        int add = (t >= off) ? sh[t - off] : 0;
        __syncthreads();
        sh[t] += add;
        __syncthreads();
    }
    if (i < n) excl[i] = sh[t] - v;
    if (t == SCAN_B - 1) btot[blockIdx.x] = sh[t];
}

__global__ void k_scan_tops(int* btot, int nb) {   // 1 block, 128 threads
    __shared__ int sh[128];
    int t = threadIdx.x;
    int v = (t < nb) ? btot[t] : 0;
    sh[t] = v;
    __syncthreads();
    for (int off = 1; off < 128; off <<= 1) {
        int add = (t >= off) ? sh[t - off] : 0;
        __syncthreads();
        sh[t] += add;
        __syncthreads();
    }
    if (t < nb) btot[t] = sh[t] - v;
}

__global__ void k_finalize(int* deg, const int* __restrict__ excl,
                           const int* __restrict__ btot,
                           int* rowp, int* cur, float* dinv, int n) {
    int i = blockIdx.x * blockDim.x + threadIdx.x;
    if (i >= n) return;
    int dg = deg[i];
    int rp = excl[i] + btot[i >> 10];
    rowp[i] = rp;
    cur[i]  = rp;
    dinv[i] = rsqrtf((float)dg + 1.0f);   // +1 self-loop
    if (i == n - 1) rowp[n] = rp + dg;
    deg[i] = 0;                            // ready for next replay
}

__global__ void k_fillcsr(const int* __restrict__ src, const int* __restrict__ dst,
                          int* cur, int* csrc, int E) {
    int e = blockIdx.x * blockDim.x + threadIdx.x;
    if (e >= E) return;
    int pos = atomicAdd(&cur[dst[e]], 1);
    csrc[pos] = src[e];
}

// ------------- CSR aggregation, fp16 gather / fp32 accumulate -------------
// warp per dst node; h rows are 128 halfs (256B), lane loads uint2 (4 halfs).
template <bool FINAL>
__global__ void k_agg16(const int* __restrict__ rowp, const int* __restrict__ csrc,
                        const float* __restrict__ dinv, const __half* __restrict__ h,
                        float* __restrict__ out,
                        const float* __restrict__ bias, const float* __restrict__ ap,
                        float* __restrict__ out2, int n) {
    int gtid = blockIdx.x * blockDim.x + threadIdx.x;
    int d = gtid >> 5, lane = gtid & 31;
    if (d >= n) return;

    float dd = dinv[d];
    float4 acc = h4tof4(reinterpret_cast<const uint2*>(h + (size_t)d * 128)[lane]);
    acc.x *= dd; acc.y *= dd; acc.z *= dd; acc.w *= dd;

    int j = rowp[d], end = rowp[d + 1];
    for (; j + 4 <= end; j += 4) {
        int s0 = csrc[j], s1 = csrc[j + 1], s2 = csrc[j + 2], s3 = csrc[j + 3];
        float w0 = dinv[s0], w1 = dinv[s1], w2 = dinv[s2], w3 = dinv[s3];
        uint2 r0 = reinterpret_cast<const uint2*>(h + (size_t)s0 * 128)[lane];
        uint2 r1 = reinterpret_cast<const uint2*>(h + (size_t)s1 * 128)[lane];
        uint2 r2 = reinterpret_cast<const uint2*>(h + (size_t)s2 * 128)[lane];
        uint2 r3 = reinterpret_cast<const uint2*>(h + (size_t)s3 * 128)[lane];
        float4 v0 = h4tof4(r0), v1 = h4tof4(r1), v2 = h4tof4(r2), v3 = h4tof4(r3);
        acc.x += w0 * v0.x + w1 * v1.x + w2 * v2.x + w3 * v3.x;
        acc.y += w0 * v0.y + w1 * v1.y + w2 * v2.y + w3 * v3.y;
        acc.z += w0 * v0.z + w1 * v1.z + w2 * v2.z + w3 * v3.z;
        acc.w += w0 * v0.w + w1 * v1.w + w2 * v2.w + w3 * v3.w;
    }
    for (; j < end; j++) {
        int s = csrc[j];
        float w = dinv[s];
        float4 v = h4tof4(reinterpret_cast<const uint2*>(h + (size_t)s * 128)[lane]);
        acc.x += w * v.x; acc.y += w * v.y; acc.z += w * v.z; acc.w += w * v.w;
    }
    acc.x *= dd; acc.y *= dd; acc.z *= dd; acc.w *= dd;

    if (FINAL) {
        float a = *ap;
        float4 bb = reinterpret_cast<const float4*>(bias)[lane];
        acc.x += bb.x; acc.y += bb.y; acc.z += bb.z; acc.w += bb.w;
        acc.x = acc.x >= 0.f ? acc.x : a * acc.x;
        acc.y = acc.y >= 0.f ? acc.y : a * acc.y;
        acc.z = acc.z >= 0.f ? acc.z : a * acc.z;
        acc.w = acc.w >= 0.f ? acc.w : a * acc.w;
        reinterpret_cast<float4*>(out2 + (size_t)d * 128)[lane] = acc;
    }
    reinterpret_cast<float4*>(out + (size_t)d * 128)[lane] = acc;
}

// ------------- tf32 tensor-core GEMM, cp.async double-buffered -------------
__device__ __forceinline__ uint32_t f2tf32(float f) {
    uint32_t u;
    asm("cvt.rna.tf32.f32 %0, %1;" : "=r"(u) : "f"(f));
    return u;
}

__device__ __forceinline__ void mma_tf32(float* c, const uint32_t* a, const uint32_t* b) {
    asm volatile(
        "mma.sync.aligned.m16n8k8.row.col.f32.tf32.tf32.f32 "
        "{%0,%1,%2,%3}, {%4,%5,%6,%7}, {%8,%9}, {%0,%1,%2,%3};"
        : "+f"(c[0]), "+f"(c[1]), "+f"(c[2]), "+f"(c[3])
        : "r"(a[0]), "r"(a[1]), "r"(a[2]), "r"(a[3]),
          "r"(b[0]), "r"(b[1]));
}

__device__ __forceinline__ void cp16(void* smem_dst, const void* gsrc, bool valid) {
    uint32_t saddr = (uint32_t)__cvta_generic_to_shared(smem_dst);
    int sz = valid ? 16 : 0;
    asm volatile("cp.async.cg.shared.global [%0], [%1], 16, %2;"
                 :: "r"(saddr), "l"(gsrc), "r"(sz));
}
#define CP_COMMIT asm volatile("cp.async.commit_group;")
#define CP_WAIT(n) asm volatile("cp.async.wait_group %0;" :: "n"(n))

// EPI: 0 raw  1 prelu(acc+bias)  2 relu(acc+bias)  3 acc+bias  5 raw->fp16(Ch)
template <int EPI>
__global__ __launch_bounds__(256) void tgemm128(
    int M, int N, int K,
    const float* __restrict__ A, const float* __restrict__ B,
    const float* __restrict__ bias, const float* __restrict__ prelu_a,
    float* __restrict__ C, __half* __restrict__ Ch)
{
    constexpr int BK = 16;
    constexpr int LDSA = 20;
    constexpr int LDSN = 136;
    __shared__ float As[2][128 * LDSA];
    __shared__ float Bs[2][BK * LDSN];

    const int tid  = threadIdx.x;
    const int lane = tid & 31;
    const int wid  = tid >> 5;
    const int g    = lane >> 2;
    const int t    = lane & 3;

    const int warpM = (wid & 1) * 64;
    const int warpN = (wid >> 1) * 32;

    const int gRow = blockIdx.y * 128;
    const int gCol = blockIdx.x * 128;

    auto issueTile = [&](int k0, int s) {
#pragma unroll
        for (int i = 0; i < 2; i++) {
            int idx = tid + i * 256;
            int m  = idx >> 2, kq = (idx & 3) << 2;
            int gm = gRow + m;
            cp16(&As[s][m * LDSA + kq], &A[(size_t)gm * K + k0 + kq], gm < M);
        }
#pragma unroll
        for (int i = 0; i < 2; i++) {
            int idx = tid + i * 256;
            int k = idx >> 5, n4 = (idx & 31) << 2;
            cp16(&Bs[s][k * LDSN + n4], &B[(size_t)(k0 + k) * N + gCol + n4], true);
        }
    };

    float c[4][4][4];
#pragma unroll
    for (int mt = 0; mt < 4; mt++)
#pragma unroll
        for (int nt = 0; nt < 4; nt++)
#pragma unroll
            for (int i = 0; i < 4; i++) c[mt][nt][i] = 0.f;

    const int T = K / BK;
    issueTile(0, 0);
    CP_COMMIT;

    for (int it = 0; it < T; it++) {
        int s = it & 1;
        if (it + 1 < T) {
            issueTile((it + 1) * BK, s ^ 1);
            CP_COMMIT;
            CP_WAIT(1);
        } else {
            CP_WAIT(0);
        }
        __syncthreads();

#pragma unroll
        for (int kk = 0; kk < BK; kk += 8) {
            uint32_t af[4][4], bf[4][2];
#pragma unroll
            for (int mt = 0; mt < 4; mt++) {
                int m0 = warpM + mt * 16 + g;
                af[mt][0] = f2tf32(As[s][(m0    ) * LDSA + kk + t    ]);
                af[mt][1] = f2tf32(As[s][(m0 + 8) * LDSA + kk + t    ]);
                af[mt][2] = f2tf32(As[s][(m0    ) * LDSA + kk + t + 4]);
                af[mt][3] = f2tf32(As[s][(m0 + 8) * LDSA + kk + t + 4]);
            }
#pragma unroll
            for (int nt = 0; nt < 4; nt++) {
                int n0 = warpN + nt * 8 + g;
                bf[nt][0] = f2tf32(Bs[s][(kk + t    ) * LDSN + n0]);
                bf[nt][1] = f2tf32(Bs[s][(kk + t + 4) * LDSN + n0]);
            }
#pragma unroll
            for (int mt = 0; mt < 4; mt++)
#pragma unroll
                for (int nt = 0; nt < 4; nt++)
                    mma_tf32(c[mt][nt], af[mt], bf[nt]);
        }
        __syncthreads();
    }

    float a_val = 0.f;
    if (EPI == 1) a_val = *prelu_a;

#pragma unroll
    for (int mt = 0; mt < 4; mt++) {
        int r0 = gRow + warpM + mt * 16 + g;
        int r1 = r0 + 8;
#pragma unroll
        for (int nt = 0; nt < 4; nt++) {
            int col = gCol + warpN + nt * 8 + t * 2;
            float v0 = c[mt][nt][0], v1 = c[mt][nt][1];
            float v2 = c[mt][nt][2], v3 = c[mt][nt][3];

            if (EPI == 1 || EPI == 2 || EPI == 3) {
                float b0 = bias[col], b1 = bias[col + 1];
                v0 += b0; v1 += b1; v2 += b0; v3 += b1;
            }
            if (EPI == 1) {
                v0 = v0 >= 0.f ? v0 : a_val * v0;
                v1 = v1 >= 0.f ? v1 : a_val * v1;
                v2 = v2 >= 0.f ? v2 : a_val * v2;
                v3 = v3 >= 0.f ? v3 : a_val * v3;
            }
            if (EPI == 2) {
                v0 = fmaxf(v0, 0.f); v1 = fmaxf(v1, 0.f);
                v2 = fmaxf(v2, 0.f); v3 = fmaxf(v3, 0.f);
            }

            if (EPI == 5) {
                if (r0 < M)
                    *reinterpret_cast<__half2*>(&Ch[(size_t)r0 * N + col]) =
                        __floats2half2_rn(v0, v1);
                if (r1 < M)
                    *reinterpret_cast<__half2*>(&Ch[(size_t)r1 * N + col]) =
                        __floats2half2_rn(v2, v3);
            } else {
                if (r0 < M)
                    *reinterpret_cast<float2*>(&C[(size_t)r0 * N + col]) = make_float2(v0, v1);
                if (r1 < M)
                    *reinterpret_cast<float2*>(&C[(size_t)r1 * N + col]) = make_float2(v2, v3);
            }
        }
    }
}

// ---- fused proj head: proj = relu(A@fc1 + b1h) @ fc2 + b2h, hidden in smem ----
__global__ __launch_bounds__(256) void k_proj(
    int M,
    const float* __restrict__ A,
    const float* __restrict__ fc1w, const float* __restrict__ fc1b,
    const float* __restrict__ fc2w, const float* __restrict__ fc2b,
    float* __restrict__ C)
{
    constexpr int BK = 16, LDSA = 20, LDSN = 136, LDH = 132, K = 128, N = 128;
    extern __shared__ float sm[];
    float* As = sm;
    float* Bs = As + 2 * 128 * LDSA;
    float* H  = Bs + 2 * BK * LDSN;

    const int tid  = threadIdx.x;
    const int lane = tid & 31;
    const int wid  = tid >> 5;
    const int g    = lane >> 2;
    const int t    = lane & 3;
    const int warpM = (wid & 1) * 64;
    const int warpN = (wid >> 1) * 32;
    const int gRow = blockIdx.y * 128;

    auto issueA = [&](int k0, int s) {
#pragma unroll
        for (int i = 0; i < 2; i++) {
            int idx = tid + i * 256;
            int m = idx >> 2, kq = (idx & 3) << 2;
            int gm = gRow + m;
            cp16(&As[s * 128 * LDSA + m * LDSA + kq], &A[(size_t)gm * K + k0 + kq], gm < M);
        }
    };
    auto issueB = [&](const float* B, int k0, int s) {
#pragma unroll
        for (int i = 0; i < 2; i++) {
            int idx = tid + i * 256;
            int k = idx >> 5, n4 = (idx & 31) << 2;
            cp16(&Bs[s * BK * LDSN + k * LDSN + n4], &B[(size_t)(k0 + k) * N + n4], true);
        }
    };

    float c[4][4][4];
    auto zeroC = [&]() {
#pragma unroll
        for (int mt = 0; mt < 4; mt++)
#pragma unroll
            for (int nt = 0; nt < 4; nt++)
#pragma unroll
                for (int i = 0; i < 4; i++) c[mt][nt][i] = 0.f;
    };

    // stage 1: H = relu(A @ fc1 + fc1b)
    zeroC();
    issueA(0, 0); issueB(fc1w, 0, 0);
    CP_COMMIT;
    const int T = K / BK;
    for (int it = 0; it < T; it++) {
        int s = it & 1;
        if (it + 1 < T) {
            issueA((it + 1) * BK, s ^ 1); issueB(fc1w, (it + 1) * BK, s ^ 1);
            CP_COMMIT; CP_WAIT(1);
        } else CP_WAIT(0);
        __syncthreads();
#pragma unroll
        for (int kk = 0; kk < BK; kk += 8) {
            uint32_t af[4][4], bf[4][2];
#pragma unroll
            for (int mt = 0; mt < 4; mt++) {
                int m0 = warpM + mt * 16 + g;
                const float* Ab = &As[s * 128 * LDSA];
                af[mt][0] = f2tf32(Ab[(m0    ) * LDSA + kk + t    ]);
                af[mt][1] = f2tf32(Ab[(m0 + 8) * LDSA + kk + t    ]);
                af[mt][2] = f2tf32(Ab[(m0    ) * LDSA + kk + t + 4]);
                af[mt][3] = f2tf32(Ab[(m0 + 8) * LDSA + kk + t + 4]);
            }
#pragma unroll
            for (int nt = 0; nt < 4; nt++) {
                int n0 = warpN + nt * 8 + g;
                const float* Bb = &Bs[s * BK * LDSN];
                bf[nt][0] = f2tf32(Bb[(kk + t    ) * LDSN + n0]);
                bf[nt][1] = f2tf32(Bb[(kk + t + 4) * LDSN + n0]);
            }
#pragma unroll
            for (int mt = 0; mt < 4; mt++)
#pragma unroll
                for (int nt = 0; nt < 4; nt++)
                    mma_tf32(c[mt][nt], af[mt], bf[nt]);
        }
        __syncthreads();
    }
#pragma unroll
    for (int mt = 0; mt < 4; mt++) {
        int m0 = warpM + mt * 16 + g;
#pragma unroll
        for (int nt = 0; nt < 4; nt++) {
            int col = warpN + nt * 8 + t * 2;
            float b0 = fc1b[col], b1 = fc1b[col + 1];
            float v0 = fmaxf(c[mt][nt][0] + b0, 0.f);
            float v1 = fmaxf(c[mt][nt][1] + b1, 0.f);
            float v2 = fmaxf(c[mt][nt][2] + b0, 0.f);
            float v3 = fmaxf(c[mt][nt][3] + b1, 0.f);
            *reinterpret_cast<float2*>(&H[(m0    ) * LDH + col]) = make_float2(v0, v1);
            *reinterpret_cast<float2*>(&H[(m0 + 8) * LDH + col]) = make_float2(v2, v3);
        }
    }
    __syncthreads();

    // stage 2: C = H @ fc2 + fc2b
    zeroC();
    issueB(fc2w, 0, 0);
    CP_COMMIT;
    for (int it = 0; it < T; it++) {
        int s = it & 1;
        if (it + 1 < T) {
            issueB(fc2w, (it + 1) * BK, s ^ 1);
            CP_COMMIT; CP_WAIT(1);
        } else CP_WAIT(0);
        __syncthreads();
        int kbase = it * BK;
#pragma unroll
        for (int kk = 0; kk < BK; kk += 8) {
            uint32_t af[4][4], bf[4][2];
#pragma unroll
            for (int mt = 0; mt < 4; mt++) {
                int m0 = warpM + mt * 16 + g;
                af[mt][0] = f2tf32(H[(m0    ) * LDH + kbase + kk + t    ]);
                af[mt][1] = f2tf32(H[(m0 + 8) * LDH + kbase + kk + t    ]);
                af[mt][2] = f2tf32(H[(m0    ) * LDH + kbase + kk + t + 4]);
                af[mt][3] = f2tf32(H[(m0 + 8) * LDH + kbase + kk + t + 4]);
            }
#pragma unroll
            for (int nt = 0; nt < 4; nt++) {
                int n0 = warpN + nt * 8 + g;
                const float* Bb = &Bs[s * BK * LDSN];
                bf[nt][0] = f2tf32(Bb[(kk + t    ) * LDSN + n0]);
                bf[nt][1] = f2tf32(Bb[(kk + t + 4) * LDSN + n0]);
            }
#pragma unroll
            for (int mt = 0; mt < 4; mt++)
#pragma unroll
                for (int nt = 0; nt < 4; nt++)
                    mma_tf32(c[mt][nt], af[mt], bf[nt]);
        }
        __syncthreads();
    }
#pragma unroll
    for (int mt = 0; mt < 4; mt++) {
        int r0 = gRow + warpM + mt * 16 + g;
        int r1 = r0 + 8;
#pragma unroll
        for (int nt = 0; nt < 4; nt++) {
            int col = warpN + nt * 8 + t * 2;
            float b0 = fc2b[col], b1 = fc2b[col + 1];
            if (r0 < M)
                *reinterpret_cast<float2*>(&C[(size_t)r0 * N + col]) =
                    make_float2(c[mt][nt][0] + b0, c[mt][nt][1] + b1);
            if (r1 < M)
                *reinterpret_cast<float2*>(&C[(size_t)r1 * N + col]) =
                    make_float2(c[mt][nt][2] + b0, c[mt][nt][3] + b1);
        }
    }
}

// ---------------- launch ----------------
extern "C" void kernel_launch(void* const* d_in, const int* in_sizes, int n_in,
                              void* d_out, int out_size) {
    const float* x    = (const float*)d_in[0];
    const int*   ei   = (const int*)d_in[1];
    const float* W1   = (const float*)d_in[2];
    const float* b1   = (const float*)d_in[3];
    const float* W2   = (const float*)d_in[4];
    const float* b2   = (const float*)d_in[5];
    const float* a    = (const float*)d_in[6];
    const float* fc1w = (const float*)d_in[7];
    const float* fc1b = (const float*)d_in[8];
    const float* fc2w = (const float*)d_in[9];
    const float* fc2b = (const float*)d_in[10];

    const int N = in_sizes[0] / 128;      // 100000 nodes
    const int E = in_sizes[1] / 2;        // 1600000 edges
    const int* src = ei;
    const int* dst = ei + E;

    float* out  = (float*)d_out;                    // [N,128]
    float* proj = out + (size_t)N * 128;            // [N,128]

    float *pd, *pagg, *pout1;
    __half* ph16;
    int *pdeg, *pexcl, *pbtot, *prowp, *pcur, *pcsrc;
    cudaGetSymbolAddress((void**)&pd,    g_dinv);
    cudaGetSymbolAddress((void**)&pagg,  g_agg);
    cudaGetSymbolAddress((void**)&pout1, g_out1);
    cudaGetSymbolAddress((void**)&ph16,  g_h16);
    cudaGetSymbolAddress((void**)&pdeg,  g_deg);
    cudaGetSymbolAddress((void**)&pexcl, g_excl);
    cudaGetSymbolAddress((void**)&pbtot, g_btot);
    cudaGetSymbolAddress((void**)&prowp, g_rowp);
    cudaGetSymbolAddress((void**)&pcur,  g_cur);
    cudaGetSymbolAddress((void**)&pcsrc, g_csrc);

    const int TPB = 256;
    const int nb  = (N + SCAN_B - 1) / SCAN_B;
    const int n4  = N * 32;
    const int aggBlocks = (N * 32 + TPB - 1) / TPB;
    const int projSmem = (2 * 128 * 20 + 2 * 16 * 136 + 128 * 132) * 4;

    cudaFuncSetAttribute(k_proj, cudaFuncAttributeMaxDynamicSharedMemorySize, projSmem);

    // ---- x -> fp16 + CSR build ----
    k_f2h<<<(n4 + TPB - 1) / TPB, TPB>>>(x, ph16, n4);
    k_hist<<<(E + TPB - 1) / TPB, TPB>>>(dst, pdeg, E);
    k_scan_blocks<<<nb, SCAN_B>>>(pdeg, pexcl, pbtot, N);
    k_scan_tops<<<1, 128>>>(pbtot, nb);
    k_finalize<<<(N + TPB - 1) / TPB, TPB>>>(pdeg, pexcl, pbtot, prowp, pcur, pd, N);
    k_fillcsr<<<(E + TPB - 1) / TPB, TPB>>>(src, dst, pcur, pcsrc, E);

    // ---- layer 1: agg(fp16 x) -> fp32 ; GEMM1 ----
    k_agg16<false><<<aggBlocks, TPB>>>(prowp, pcsrc, pd, ph16, pagg,
                                       nullptr, nullptr, nullptr, N);
    dim3 grid1(2, (N + 127) / 128);
    dim3 grid2(1, (N + 127) / 128);
    tgemm128<1><<<grid1, 256>>>(N, 256, 128, pagg, W1, b1, a, pout1, nullptr);

    // ---- layer 2: h2 = out1 @ W2 stored fp16 (reuses g_h16) ; agg final ----
    tgemm128<5><<<grid2, 256>>>(N, 128, 256, pout1, W2, nullptr, nullptr, nullptr, ph16);
    k_agg16<true><<<aggBlocks, TPB>>>(prowp, pcsrc, pd, ph16, pagg,
                                      b2, a, out, N);

    // ---- fused proj head ----
    k_proj<<<grid2, 256, projSmem>>>(N, pagg, fc1w, fc1b, fc2w, fc2b, proj);
}

// round 12
// speedup vs baseline: 4.8068x; 1.0608x over previous
#include <cuda_runtime.h>
#include <cuda_fp16.h>
#include <cstdint>

// ---------------- static scratch (no allocations allowed) ----------------
#define MAXN 100000
#define MAXE 1600000
#define SCAN_B 1024

__device__ float  g_dinv[MAXN];
__device__ float  g_agg [MAXN * 128];     // agg results (fp32)
__device__ float  g_out1[MAXN * 256];     // layer-1 output
__device__ __half g_h16 [MAXN * 128];     // fp16 PRESCALED gather buffer
__device__ int    g_deg [MAXN];           // zero at entry; re-zeroed in k_finalize
__device__ int    g_excl[MAXN];
__device__ int    g_btot[128];
__device__ int    g_rowp[MAXN + 1];
__device__ int    g_cur [MAXN];
__device__ int    g_csrc[MAXE];

// ---------------- fp16 helpers ----------------
__device__ __forceinline__ float4 h4tof4(uint2 r) {
    __half2 p0 = *reinterpret_cast<__half2*>(&r.x);
    __half2 p1 = *reinterpret_cast<__half2*>(&r.y);
    float2 f0 = __half22float2(p0);
    float2 f1 = __half22float2(p1);
    return make_float4(f0.x, f0.y, f1.x, f1.y);
}

// xh[row] = fp16( x[row] * dinv[row] )   (prescaled gather buffer)
__global__ void k_f2h_scaled(const float* __restrict__ x,
                             const float* __restrict__ dinv,
                             __half* __restrict__ xh, int n4) {
    int i = blockIdx.x * blockDim.x + threadIdx.x;
    if (i >= n4) return;
    float s = dinv[i >> 5];
    float4 v = reinterpret_cast<const float4*>(x)[i];
    __half2 p0 = __floats2half2_rn(v.x * s, v.y * s);
    __half2 p1 = __floats2half2_rn(v.z * s, v.w * s);
    uint2 r;
    r.x = *reinterpret_cast<uint32_t*>(&p0);
    r.y = *reinterpret_cast<uint32_t*>(&p1);
    reinterpret_cast<uint2*>(xh)[i] = r;
}

// ---------------- CSR build ----------------
__global__ void k_hist(const int* __restrict__ dst, int* deg, int E) {
    int e = blockIdx.x * blockDim.x + threadIdx.x;
    if (e < E) atomicAdd(&deg[dst[e]], 1);
}

__global__ void k_scan_blocks(const int* __restrict__ deg, int* excl,
                              int* btot, int n) {
    __shared__ int sh[SCAN_B];
    int t = threadIdx.x;
    int i = blockIdx.x * SCAN_B + t;
    int v = (i < n) ? deg[i] : 0;
    sh[t] = v;
    __syncthreads();
    for (int off = 1; off < SCAN_B; off <<= 1) {
        int add = (t >= off) ? sh[t - off] : 0;
        __syncthreads();
        sh[t] += add;
        __syncthreads();
    }
    if (i < n) excl[i] = sh[t] - v;
    if (t == SCAN_B - 1) btot[blockIdx.x] = sh[t];
}

__global__ void k_scan_tops(int* btot, int nb) {   // 1 block, 128 threads
    __shared__ int sh[128];
    int t = threadIdx.x;
    int v = (t < nb) ? btot[t] : 0;
    sh[t] = v;
    __syncthreads();
    for (int off = 1; off < 128; off <<= 1) {
        int add = (t >= off) ? sh[t - off] : 0;
        __syncthreads();
        sh[t] += add;
        __syncthreads();
    }
    if (t < nb) btot[t] = sh[t] - v;
}

__global__ void k_finalize(int* deg, const int* __restrict__ excl,
                           const int* __restrict__ btot,
                           int* rowp, int* cur, float* dinv, int n) {
    int i = blockIdx.x * blockDim.x + threadIdx.x;
    if (i >= n) return;
    int dg = deg[i];
    int rp = excl[i] + btot[i >> 10];
    rowp[i] = rp;
    cur[i]  = rp;
    dinv[i] = rsqrtf((float)dg + 1.0f);   // +1 self-loop
    if (i == n - 1) rowp[n] = rp + dg;
    deg[i] = 0;                            // ready for next replay
}

__global__ void k_fillcsr(const int* __restrict__ src, const int* __restrict__ dst,
                          int* cur, int* csrc, int E) {
    int e = blockIdx.x * blockDim.x + threadIdx.x;
    if (e >= E) return;
    int pos = atomicAdd(&cur[dst[e]], 1);
    csrc[pos] = src[e];
}

// -------- CSR aggregation over PRESCALED fp16 rows, warp per dst node --------
// out[d] = dinv[d] * ( p[d] + sum_s p[s] ),  p = prescaled rows in h.
template <bool FINAL>
__global__ void k_agg16(const int* __restrict__ rowp, const int* __restrict__ csrc,
                        const float* __restrict__ dinv, const __half* __restrict__ h,
                        float* __restrict__ out,
                        const float* __restrict__ bias, const float* __restrict__ ap,
                        float* __restrict__ out2, int n) {
    int gtid = blockIdx.x * blockDim.x + threadIdx.x;
    int d = gtid >> 5, lane = gtid & 31;
    if (d >= n) return;

    float4 acc = h4tof4(reinterpret_cast<const uint2*>(h + (size_t)d * 128)[lane]);

    int j = rowp[d], end = rowp[d + 1];
    for (; j + 8 <= end; j += 8) {
        int s[8];
#pragma unroll
        for (int u = 0; u < 8; u++) s[u] = csrc[j + u];
        uint2 r[8];
#pragma unroll
        for (int u = 0; u < 8; u++)
            r[u] = reinterpret_cast<const uint2*>(h + (size_t)s[u] * 128)[lane];
#pragma unroll
        for (int u = 0; u < 8; u++) {
            float4 v = h4tof4(r[u]);
            acc.x += v.x; acc.y += v.y; acc.z += v.z; acc.w += v.w;
        }
    }
    if (j + 4 <= end) {
        int s[4];
#pragma unroll
        for (int u = 0; u < 4; u++) s[u] = csrc[j + u];
        uint2 r[4];
#pragma unroll
        for (int u = 0; u < 4; u++)
            r[u] = reinterpret_cast<const uint2*>(h + (size_t)s[u] * 128)[lane];
#pragma unroll
        for (int u = 0; u < 4; u++) {
            float4 v = h4tof4(r[u]);
            acc.x += v.x; acc.y += v.y; acc.z += v.z; acc.w += v.w;
        }
        j += 4;
    }
    for (; j < end; j++) {
        float4 v = h4tof4(reinterpret_cast<const uint2*>(h + (size_t)csrc[j] * 128)[lane]);
        acc.x += v.x; acc.y += v.y; acc.z += v.z; acc.w += v.w;
    }

    float dd = dinv[d];
    acc.x *= dd; acc.y *= dd; acc.z *= dd; acc.w *= dd;

    if (FINAL) {
        float a = *ap;
        float4 bb = reinterpret_cast<const float4*>(bias)[lane];
        acc.x += bb.x; acc.y += bb.y; acc.z += bb.z; acc.w += bb.w;
        acc.x = acc.x >= 0.f ? acc.x : a * acc.x;
        acc.y = acc.y >= 0.f ? acc.y : a * acc.y;
        acc.z = acc.z >= 0.f ? acc.z : a * acc.z;
        acc.w = acc.w >= 0.f ? acc.w : a * acc.w;
        reinterpret_cast<float4*>(out2 + (size_t)d * 128)[lane] = acc;
    }
    reinterpret_cast<float4*>(out + (size_t)d * 128)[lane] = acc;
}

// ------------- tf32 tensor-core GEMM, cp.async double-buffered -------------
__device__ __forceinline__ uint32_t f2tf32(float f) {
    uint32_t u;
    asm("cvt.rna.tf32.f32 %0, %1;" : "=r"(u) : "f"(f));
    return u;
}

__device__ __forceinline__ void mma_tf32(float* c, const uint32_t* a, const uint32_t* b) {
    asm volatile(
        "mma.sync.aligned.m16n8k8.row.col.f32.tf32.tf32.f32 "
        "{%0,%1,%2,%3}, {%4,%5,%6,%7}, {%8,%9}, {%0,%1,%2,%3};"
        : "+f"(c[0]), "+f"(c[1]), "+f"(c[2]), "+f"(c[3])
        : "r"(a[0]), "r"(a[1]), "r"(a[2]), "r"(a[3]),
          "r"(b[0]), "r"(b[1]));
}

__device__ __forceinline__ void cp16(void* smem_dst, const void* gsrc, bool valid) {
    uint32_t saddr = (uint32_t)__cvta_generic_to_shared(smem_dst);
    int sz = valid ? 16 : 0;
    asm volatile("cp.async.cg.shared.global [%0], [%1], 16, %2;"
                 :: "r"(saddr), "l"(gsrc), "r"(sz));
}
#define CP_COMMIT asm volatile("cp.async.commit_group;")
#define CP_WAIT(n) asm volatile("cp.async.wait_group %0;" :: "n"(n))

// EPI: 0 raw  1 prelu(acc+bias)  2 relu(acc+bias)  3 acc+bias
//      5 fp16(acc * dinv[row]) -> Ch  (prescaled gather buffer)
template <int EPI>
__global__ __launch_bounds__(256) void tgemm128(
    int M, int N, int K,
    const float* __restrict__ A, const float* __restrict__ B,
    const float* __restrict__ bias, const float* __restrict__ prelu_a,
    const float* __restrict__ dinvp,
    float* __restrict__ C, __half* __restrict__ Ch)
{
    constexpr int BK = 16;
    constexpr int LDSA = 20;
    constexpr int LDSN = 136;
    __shared__ float As[2][128 * LDSA];
    __shared__ float Bs[2][BK * LDSN];

    const int tid  = threadIdx.x;
    const int lane = tid & 31;
    const int wid  = tid >> 5;
    const int g    = lane >> 2;
    const int t    = lane & 3;

    const int warpM = (wid & 1) * 64;
    const int warpN = (wid >> 1) * 32;

    const int gRow = blockIdx.y * 128;
    const int gCol = blockIdx.x * 128;

    auto issueTile = [&](int k0, int s) {
#pragma unroll
        for (int i = 0; i < 2; i++) {
            int idx = tid + i * 256;
            int m  = idx >> 2, kq = (idx & 3) << 2;
            int gm = gRow + m;
            cp16(&As[s][m * LDSA + kq], &A[(size_t)gm * K + k0 + kq], gm < M);
        }
#pragma unroll
        for (int i = 0; i < 2; i++) {
            int idx = tid + i * 256;
            int k = idx >> 5, n4 = (idx & 31) << 2;
            cp16(&Bs[s][k * LDSN + n4], &B[(size_t)(k0 + k) * N + gCol + n4], true);
        }
    };

    float c[4][4][4];
#pragma unroll
    for (int mt = 0; mt < 4; mt++)
#pragma unroll
        for (int nt = 0; nt < 4; nt++)
#pragma unroll
            for (int i = 0; i < 4; i++) c[mt][nt][i] = 0.f;

    const int T = K / BK;
    issueTile(0, 0);
    CP_COMMIT;

    for (int it = 0; it < T; it++) {
        int s = it & 1;
        if (it + 1 < T) {
            issueTile((it + 1) * BK, s ^ 1);
            CP_COMMIT;
            CP_WAIT(1);
        } else {
            CP_WAIT(0);
        }
        __syncthreads();

#pragma unroll
        for (int kk = 0; kk < BK; kk += 8) {
            uint32_t af[4][4], bf[4][2];
#pragma unroll
            for (int mt = 0; mt < 4; mt++) {
                int m0 = warpM + mt * 16 + g;
                af[mt][0] = f2tf32(As[s][(m0    ) * LDSA + kk + t    ]);
                af[mt][1] = f2tf32(As[s][(m0 + 8) * LDSA + kk + t    ]);
                af[mt][2] = f2tf32(As[s][(m0    ) * LDSA + kk + t + 4]);
                af[mt][3] = f2tf32(As[s][(m0 + 8) * LDSA + kk + t + 4]);
            }
#pragma unroll
            for (int nt = 0; nt < 4; nt++) {
                int n0 = warpN + nt * 8 + g;
                bf[nt][0] = f2tf32(Bs[s][(kk + t    ) * LDSN + n0]);
                bf[nt][1] = f2tf32(Bs[s][(kk + t + 4) * LDSN + n0]);
            }
#pragma unroll
            for (int mt = 0; mt < 4; mt++)
#pragma unroll
                for (int nt = 0; nt < 4; nt++)
                    mma_tf32(c[mt][nt], af[mt], bf[nt]);
        }
        __syncthreads();
    }

    float a_val = 0.f;
    if (EPI == 1) a_val = *prelu_a;

#pragma unroll
    for (int mt = 0; mt < 4; mt++) {
        int r0 = gRow + warpM + mt * 16 + g;
        int r1 = r0 + 8;
        float s0 = 1.f, s1 = 1.f;
        if (EPI == 5) {
            if (r0 < M) s0 = dinvp[r0];
            if (r1 < M) s1 = dinvp[r1];
        }
#pragma unroll
        for (int nt = 0; nt < 4; nt++) {
            int col = gCol + warpN + nt * 8 + t * 2;
            float v0 = c[mt][nt][0], v1 = c[mt][nt][1];
            float v2 = c[mt][nt][2], v3 = c[mt][nt][3];

            if (EPI == 1 || EPI == 2 || EPI == 3) {
                float b0 = bias[col], b1 = bias[col + 1];
                v0 += b0; v1 += b1; v2 += b0; v3 += b1;
            }
            if (EPI == 1) {
                v0 = v0 >= 0.f ? v0 : a_val * v0;
                v1 = v1 >= 0.f ? v1 : a_val * v1;
                v2 = v2 >= 0.f ? v2 : a_val * v2;
                v3 = v3 >= 0.f ? v3 : a_val * v3;
            }
            if (EPI == 2) {
                v0 = fmaxf(v0, 0.f); v1 = fmaxf(v1, 0.f);
                v2 = fmaxf(v2, 0.f); v3 = fmaxf(v3, 0.f);
            }

            if (EPI == 5) {
                if (r0 < M)
                    *reinterpret_cast<__half2*>(&Ch[(size_t)r0 * N + col]) =
                        __floats2half2_rn(v0 * s0, v1 * s0);
                if (r1 < M)
                    *reinterpret_cast<__half2*>(&Ch[(size_t)r1 * N + col]) =
                        __floats2half2_rn(v2 * s1, v3 * s1);
            } else {
                if (r0 < M)
                    *reinterpret_cast<float2*>(&C[(size_t)r0 * N + col]) = make_float2(v0, v1);
                if (r1 < M)
                    *reinterpret_cast<float2*>(&C[(size_t)r1 * N + col]) = make_float2(v2, v3);
            }
        }
    }
}

// ---- fused proj head: proj = relu(A@fc1 + b1h) @ fc2 + b2h, hidden in smem ----
__global__ __launch_bounds__(256) void k_proj(
    int M,
    const float* __restrict__ A,
    const float* __restrict__ fc1w, const float* __restrict__ fc1b,
    const float* __restrict__ fc2w, const float* __restrict__ fc2b,
    float* __restrict__ C)
{
    constexpr int BK = 16, LDSA = 20, LDSN = 136, LDH = 132, K = 128, N = 128;
    extern __shared__ float sm[];
    float* As = sm;
    float* Bs = As + 2 * 128 * LDSA;
    float* H  = Bs + 2 * BK * LDSN;

    const int tid  = threadIdx.x;
    const int lane = tid & 31;
    const int wid  = tid >> 5;
    const int g    = lane >> 2;
    const int t    = lane & 3;
    const int warpM = (wid & 1) * 64;
    const int warpN = (wid >> 1) * 32;
    const int gRow = blockIdx.y * 128;

    auto issueA = [&](int k0, int s) {
#pragma unroll
        for (int i = 0; i < 2; i++) {
            int idx = tid + i * 256;
            int m = idx >> 2, kq = (idx & 3) << 2;
            int gm = gRow + m;
            cp16(&As[s * 128 * LDSA + m * LDSA + kq], &A[(size_t)gm * K + k0 + kq], gm < M);
        }
    };
    auto issueB = [&](const float* B, int k0, int s) {
#pragma unroll
        for (int i = 0; i < 2; i++) {
            int idx = tid + i * 256;
            int k = idx >> 5, n4 = (idx & 31) << 2;
            cp16(&Bs[s * BK * LDSN + k * LDSN + n4], &B[(size_t)(k0 + k) * N + n4], true);
        }
    };

    float c[4][4][4];
    auto zeroC = [&]() {
#pragma unroll
        for (int mt = 0; mt < 4; mt++)
#pragma unroll
            for (int nt = 0; nt < 4; nt++)
#pragma unroll
                for (int i = 0; i < 4; i++) c[mt][nt][i] = 0.f;
    };

    // stage 1: H = relu(A @ fc1 + fc1b)
    zeroC();
    issueA(0, 0); issueB(fc1w, 0, 0);
    CP_COMMIT;
    const int T = K / BK;
    for (int it = 0; it < T; it++) {
        int s = it & 1;
        if (it + 1 < T) {
            issueA((it + 1) * BK, s ^ 1); issueB(fc1w, (it + 1) * BK, s ^ 1);
            CP_COMMIT; CP_WAIT(1);
        } else CP_WAIT(0);
        __syncthreads();
#pragma unroll
        for (int kk = 0; kk < BK; kk += 8) {
            uint32_t af[4][4], bf[4][2];
#pragma unroll
            for (int mt = 0; mt < 4; mt++) {
                int m0 = warpM + mt * 16 + g;
                const float* Ab = &As[s * 128 * LDSA];
                af[mt][0] = f2tf32(Ab[(m0    ) * LDSA + kk + t    ]);
                af[mt][1] = f2tf32(Ab[(m0 + 8) * LDSA + kk + t    ]);
                af[mt][2] = f2tf32(Ab[(m0    ) * LDSA + kk + t + 4]);
                af[mt][3] = f2tf32(Ab[(m0 + 8) * LDSA + kk + t + 4]);
            }
#pragma unroll
            for (int nt = 0; nt < 4; nt++) {
                int n0 = warpN + nt * 8 + g;
                const float* Bb = &Bs[s * BK * LDSN];
                bf[nt][0] = f2tf32(Bb[(kk + t    ) * LDSN + n0]);
                bf[nt][1] = f2tf32(Bb[(kk + t + 4) * LDSN + n0]);
            }
#pragma unroll
            for (int mt = 0; mt < 4; mt++)
#pragma unroll
                for (int nt = 0; nt < 4; nt++)
                    mma_tf32(c[mt][nt], af[mt], bf[nt]);
        }
        __syncthreads();
    }
#pragma unroll
    for (int mt = 0; mt < 4; mt++) {
        int m0 = warpM + mt * 16 + g;
#pragma unroll
        for (int nt = 0; nt < 4; nt++) {
            int col = warpN + nt * 8 + t * 2;
            float b0 = fc1b[col], b1 = fc1b[col + 1];
            float v0 = fmaxf(c[mt][nt][0] + b0, 0.f);
            float v1 = fmaxf(c[mt][nt][1] + b1, 0.f);
            float v2 = fmaxf(c[mt][nt][2] + b0, 0.f);
            float v3 = fmaxf(c[mt][nt][3] + b1, 0.f);
            *reinterpret_cast<float2*>(&H[(m0    ) * LDH + col]) = make_float2(v0, v1);
            *reinterpret_cast<float2*>(&H[(m0 + 8) * LDH + col]) = make_float2(v2, v3);
        }
    }
    __syncthreads();

    // stage 2: C = H @ fc2 + fc2b
    zeroC();
    issueB(fc2w, 0, 0);
    CP_COMMIT;
    for (int it = 0; it < T; it++) {
        int s = it & 1;
        if (it + 1 < T) {
            issueB(fc2w, (it + 1) * BK, s ^ 1);
            CP_COMMIT; CP_WAIT(1);
        } else CP_WAIT(0);
        __syncthreads();
        int kbase = it * BK;
#pragma unroll
        for (int kk = 0; kk < BK; kk += 8) {
            uint32_t af[4][4], bf[4][2];
#pragma unroll
            for (int mt = 0; mt < 4; mt++) {
                int m0 = warpM + mt * 16 + g;
                af[mt][0] = f2tf32(H[(m0    ) * LDH + kbase + kk + t    ]);
                af[mt][1] = f2tf32(H[(m0 + 8) * LDH + kbase + kk + t    ]);
                af[mt][2] = f2tf32(H[(m0    ) * LDH + kbase + kk + t + 4]);
                af[mt][3] = f2tf32(H[(m0 + 8) * LDH + kbase + kk + t + 4]);
            }
#pragma unroll
            for (int nt = 0; nt < 4; nt++) {
                int n0 = warpN + nt * 8 + g;
                const float* Bb = &Bs[s * BK * LDSN];
                bf[nt][0] = f2tf32(Bb[(kk + t    ) * LDSN + n0]);
                bf[nt][1] = f2tf32(Bb[(kk + t + 4) * LDSN + n0]);
            }
#pragma unroll
            for (int mt = 0; mt < 4; mt++)
#pragma unroll
                for (int nt = 0; nt < 4; nt++)
                    mma_tf32(c[mt][nt], af[mt], bf[nt]);
        }
        __syncthreads();
    }
#pragma unroll
    for (int mt = 0; mt < 4; mt++) {
        int r0 = gRow + warpM + mt * 16 + g;
        int r1 = r0 + 8;
#pragma unroll
        for (int nt = 0; nt < 4; nt++) {
            int col = warpN + nt * 8 + t * 2;
            float b0 = fc2b[col], b1 = fc2b[col + 1];
            if (r0 < M)
                *reinterpret_cast<float2*>(&C[(size_t)r0 * N + col]) =
                    make_float2(c[mt][nt][0] + b0, c[mt][nt][1] + b1);
            if (r1 < M)
                *reinterpret_cast<float2*>(&C[(size_t)r1 * N + col]) =
                    make_float2(c[mt][nt][2] + b0, c[mt][nt][3] + b1);
        }
    }
}

// ---------------- launch ----------------
extern "C" void kernel_launch(void* const* d_in, const int* in_sizes, int n_in,
                              void* d_out, int out_size) {
    const float* x    = (const float*)d_in[0];
    const int*   ei   = (const int*)d_in[1];
    const float* W1   = (const float*)d_in[2];
    const float* b1   = (const float*)d_in[3];
    const float* W2   = (const float*)d_in[4];
    const float* b2   = (const float*)d_in[5];
    const float* a    = (const float*)d_in[6];
    const float* fc1w = (const float*)d_in[7];
    const float* fc1b = (const float*)d_in[8];
    const float* fc2w = (const float*)d_in[9];
    const float* fc2b = (const float*)d_in[10];

    const int N = in_sizes[0] / 128;      // 100000 nodes
    const int E = in_sizes[1] / 2;        // 1600000 edges
    const int* src = ei;
    const int* dst = ei + E;

    float* out  = (float*)d_out;                    // [N,128]
    float* proj = out + (size_t)N * 128;            // [N,128]

    float *pd, *pagg, *pout1;
    __half* ph16;
    int *pdeg, *pexcl, *pbtot, *prowp, *pcur, *pcsrc;
    cudaGetSymbolAddress((void**)&pd,    g_dinv);
    cudaGetSymbolAddress((void**)&pagg,  g_agg);
    cudaGetSymbolAddress((void**)&pout1, g_out1);
    cudaGetSymbolAddress((void**)&ph16,  g_h16);
    cudaGetSymbolAddress((void**)&pdeg,  g_deg);
    cudaGetSymbolAddress((void**)&pexcl, g_excl);
    cudaGetSymbolAddress((void**)&pbtot, g_btot);
    cudaGetSymbolAddress((void**)&prowp, g_rowp);
    cudaGetSymbolAddress((void**)&pcur,  g_cur);
    cudaGetSymbolAddress((void**)&pcsrc, g_csrc);

    const int TPB = 256;
    const int nb  = (N + SCAN_B - 1) / SCAN_B;
    const int n4  = N * 32;
    const int aggBlocks = (N * 32 + TPB - 1) / TPB;
    const int projSmem = (2 * 128 * 20 + 2 * 16 * 136 + 128 * 132) * 4;

    cudaFuncSetAttribute(k_proj, cudaFuncAttributeMaxDynamicSharedMemorySize, projSmem);

    // ---- CSR build (dinv needed before prescaled f2h) ----
    k_hist<<<(E + TPB - 1) / TPB, TPB>>>(dst, pdeg, E);
    k_scan_blocks<<<nb, SCAN_B>>>(pdeg, pexcl, pbtot, N);
    k_scan_tops<<<1, 128>>>(pbtot, nb);
    k_finalize<<<(N + TPB - 1) / TPB, TPB>>>(pdeg, pexcl, pbtot, prowp, pcur, pd, N);
    k_f2h_scaled<<<(n4 + TPB - 1) / TPB, TPB>>>(x, pd, ph16, n4);
    k_fillcsr<<<(E + TPB - 1) / TPB, TPB>>>(src, dst, pcur, pcsrc, E);

    // ---- layer 1: agg(prescaled x16) -> fp32 ; GEMM1 ----
    k_agg16<false><<<aggBlocks, TPB>>>(prowp, pcsrc, pd, ph16, pagg,
                                       nullptr, nullptr, nullptr, N);
    dim3 grid1(2, (N + 127) / 128);
    dim3 grid2(1, (N + 127) / 128);
    tgemm128<1><<<grid1, 256>>>(N, 256, 128, pagg, W1, b1, a, nullptr, pout1, nullptr);

    // ---- layer 2: h2 = (out1 @ W2) * dinv stored fp16 ; agg final ----
    tgemm128<5><<<grid2, 256>>>(N, 128, 256, pout1, W2, nullptr, nullptr, pd, nullptr, ph16);
    k_agg16<true><<<aggBlocks, TPB>>>(prowp, pcsrc, pd, ph16, pagg,
                                      b2, a, out, N);

    // ---- fused proj head ----
    k_proj<<<grid2, 256, projSmem>>>(N, pagg, fc1w, fc1b, fc2w, fc2b, proj);
}

// round 13
// speedup vs baseline: 4.8117x; 1.0010x over previous
#include <cuda_runtime.h>
#include <cuda_fp16.h>
#include <cstdint>

// ---------------- static scratch (no allocations allowed) ----------------
#define MAXN 100000
#define MAXE 1600000
#define SCAN_B 1024

__device__ float  g_dinv[MAXN];
__device__ float  g_agg [MAXN * 128];     // agg results (fp32)
__device__ float  g_out1[MAXN * 256];     // layer-1 output
__device__ __half g_h16 [MAXN * 128];     // fp16 PRESCALED gather buffer
__device__ int    g_deg [MAXN];           // zero at entry; re-zeroed in k_finalize
__device__ int    g_excl[MAXN];
__device__ int    g_btot[128];
__device__ int    g_rowp[MAXN + 1];
__device__ int    g_cur [MAXN];
__device__ int    g_csrc[MAXE];

// ---------------- fp16 helpers ----------------
__device__ __forceinline__ float4 h4tof4(uint2 r) {
    __half2 p0 = *reinterpret_cast<__half2*>(&r.x);
    __half2 p1 = *reinterpret_cast<__half2*>(&r.y);
    float2 f0 = __half22float2(p0);
    float2 f1 = __half22float2(p1);
    return make_float4(f0.x, f0.y, f1.x, f1.y);
}

// xh[row] = fp16( x[row] * dinv[row] )   (prescaled gather buffer)
__global__ void k_f2h_scaled(const float* __restrict__ x,
                             const float* __restrict__ dinv,
                             __half* __restrict__ xh, int n4) {
    int i = blockIdx.x * blockDim.x + threadIdx.x;
    if (i >= n4) return;
    float s = dinv[i >> 5];
    float4 v = reinterpret_cast<const float4*>(x)[i];
    __half2 p0 = __floats2half2_rn(v.x * s, v.y * s);
    __half2 p1 = __floats2half2_rn(v.z * s, v.w * s);
    uint2 r;
    r.x = *reinterpret_cast<uint32_t*>(&p0);
    r.y = *reinterpret_cast<uint32_t*>(&p1);
    reinterpret_cast<uint2*>(xh)[i] = r;
}

// ---------------- CSR build ----------------
__global__ void k_hist(const int* __restrict__ dst, int* deg, int E) {
    int e = blockIdx.x * blockDim.x + threadIdx.x;
    if (e < E) atomicAdd(&deg[dst[e]], 1);
}

__global__ void k_scan_blocks(const int* __restrict__ deg, int* excl,
                              int* btot, int n) {
    __shared__ int sh[SCAN_B];
    int t = threadIdx.x;
    int i = blockIdx.x * SCAN_B + t;
    int v = (i < n) ? deg[i] : 0;
    sh[t] = v;
    __syncthreads();
    for (int off = 1; off < SCAN_B; off <<= 1) {
        int add = (t >= off) ? sh[t - off] : 0;
        __syncthreads();
        sh[t] += add;
        __syncthreads();
    }
    if (i < n) excl[i] = sh[t] - v;
    if (t == SCAN_B - 1) btot[blockIdx.x] = sh[t];
}

__global__ void k_scan_tops(int* btot, int nb) {   // 1 block, 128 threads
    __shared__ int sh[128];
    int t = threadIdx.x;
    int v = (t < nb) ? btot[t] : 0;
    sh[t] = v;
    __syncthreads();
    for (int off = 1; off < 128; off <<= 1) {
        int add = (t >= off) ? sh[t - off] : 0;
        __syncthreads();
        sh[t] += add;
        __syncthreads();
    }
    if (t < nb) btot[t] = sh[t] - v;
}

__global__ void k_finalize(int* deg, const int* __restrict__ excl,
                           const int* __restrict__ btot,
                           int* rowp, int* cur, float* dinv, int n) {
    int i = blockIdx.x * blockDim.x + threadIdx.x;
    if (i >= n) return;
    int dg = deg[i];
    int rp = excl[i] + btot[i >> 10];
    rowp[i] = rp;
    cur[i]  = rp;
    dinv[i] = rsqrtf((float)dg + 1.0f);   // +1 self-loop
    if (i == n - 1) rowp[n] = rp + dg;
    deg[i] = 0;                            // ready for next replay
}

__global__ void k_fillcsr(const int* __restrict__ src, const int* __restrict__ dst,
                          int* cur, int* csrc, int E) {
    int e = blockIdx.x * blockDim.x + threadIdx.x;
    if (e >= E) return;
    int pos = atomicAdd(&cur[dst[e]], 1);
    csrc[pos] = src[e];
}

// -------- CSR aggregation over PRESCALED fp16 rows, warp per dst node --------
// out[d] = dinv[d] * ( p[d] + sum_s p[s] ),  p = prescaled rows in h.
// Unroll-16 staged loads: 16 broadcast idx loads, 16 independent row gathers,
// then accumulate — maximizes MLP per warp (latency-bound loop).
template <bool FINAL>
__global__ void k_agg16(const int* __restrict__ rowp, const int* __restrict__ csrc,
                        const float* __restrict__ dinv, const __half* __restrict__ h,
                        float* __restrict__ out,
                        const float* __restrict__ bias, const float* __restrict__ ap,
                        float* __restrict__ out2, int n) {
    int gtid = blockIdx.x * blockDim.x + threadIdx.x;
    int d = gtid >> 5, lane = gtid & 31;
    if (d >= n) return;

    float4 acc = h4tof4(reinterpret_cast<const uint2*>(h + (size_t)d * 128)[lane]);

    int j = rowp[d], end = rowp[d + 1];
    for (; j + 16 <= end; j += 16) {
        int s[16];
#pragma unroll
        for (int u = 0; u < 16; u++) s[u] = csrc[j + u];
        uint2 r[16];
#pragma unroll
        for (int u = 0; u < 16; u++)
            r[u] = reinterpret_cast<const uint2*>(h + (size_t)s[u] * 128)[lane];
#pragma unroll
        for (int u = 0; u < 16; u++) {
            float4 v = h4tof4(r[u]);
            acc.x += v.x; acc.y += v.y; acc.z += v.z; acc.w += v.w;
        }
    }
    if (j + 8 <= end) {
        int s[8];
#pragma unroll
        for (int u = 0; u < 8; u++) s[u] = csrc[j + u];
        uint2 r[8];
#pragma unroll
        for (int u = 0; u < 8; u++)
            r[u] = reinterpret_cast<const uint2*>(h + (size_t)s[u] * 128)[lane];
#pragma unroll
        for (int u = 0; u < 8; u++) {
            float4 v = h4tof4(r[u]);
            acc.x += v.x; acc.y += v.y; acc.z += v.z; acc.w += v.w;
        }
        j += 8;
    }
    if (j + 4 <= end) {
        int s[4];
#pragma unroll
        for (int u = 0; u < 4; u++) s[u] = csrc[j + u];
        uint2 r[4];
#pragma unroll
        for (int u = 0; u < 4; u++)
            r[u] = reinterpret_cast<const uint2*>(h + (size_t)s[u] * 128)[lane];
#pragma unroll
        for (int u = 0; u < 4; u++) {
            float4 v = h4tof4(r[u]);
            acc.x += v.x; acc.y += v.y; acc.z += v.z; acc.w += v.w;
        }
        j += 4;
    }
    for (; j < end; j++) {
        float4 v = h4tof4(reinterpret_cast<const uint2*>(h + (size_t)csrc[j] * 128)[lane]);
        acc.x += v.x; acc.y += v.y; acc.z += v.z; acc.w += v.w;
    }

    float dd = dinv[d];
    acc.x *= dd; acc.y *= dd; acc.z *= dd; acc.w *= dd;

    if (FINAL) {
        float a = *ap;
        float4 bb = reinterpret_cast<const float4*>(bias)[lane];
        acc.x += bb.x; acc.y += bb.y; acc.z += bb.z; acc.w += bb.w;
        acc.x = acc.x >= 0.f ? acc.x : a * acc.x;
        acc.y = acc.y >= 0.f ? acc.y : a * acc.y;
        acc.z = acc.z >= 0.f ? acc.z : a * acc.z;
        acc.w = acc.w >= 0.f ? acc.w : a * acc.w;
        reinterpret_cast<float4*>(out2 + (size_t)d * 128)[lane] = acc;
    }
    reinterpret_cast<float4*>(out + (size_t)d * 128)[lane] = acc;
}

// ------------- tf32 tensor-core GEMM, cp.async double-buffered -------------
__device__ __forceinline__ uint32_t f2tf32(float f) {
    uint32_t u;
    asm("cvt.rna.tf32.f32 %0, %1;" : "=r"(u) : "f"(f));
    return u;
}

__device__ __forceinline__ void mma_tf32(float* c, const uint32_t* a, const uint32_t* b) {
    asm volatile(
        "mma.sync.aligned.m16n8k8.row.col.f32.tf32.tf32.f32 "
        "{%0,%1,%2,%3}, {%4,%5,%6,%7}, {%8,%9}, {%0,%1,%2,%3};"
        : "+f"(c[0]), "+f"(c[1]), "+f"(c[2]), "+f"(c[3])
        : "r"(a[0]), "r"(a[1]), "r"(a[2]), "r"(a[3]),
          "r"(b[0]), "r"(b[1]));
}

__device__ __forceinline__ void cp16(void* smem_dst, const void* gsrc, bool valid) {
    uint32_t saddr = (uint32_t)__cvta_generic_to_shared(smem_dst);
    int sz = valid ? 16 : 0;
    asm volatile("cp.async.cg.shared.global [%0], [%1], 16, %2;"
                 :: "r"(saddr), "l"(gsrc), "r"(sz));
}
#define CP_COMMIT asm volatile("cp.async.commit_group;")
#define CP_WAIT(n) asm volatile("cp.async.wait_group %0;" :: "n"(n))

// EPI: 0 raw  1 prelu(acc+bias)  2 relu(acc+bias)  3 acc+bias
//      5 fp16(acc * dinv[row]) -> Ch  (prescaled gather buffer)
template <int EPI>
__global__ __launch_bounds__(256) void tgemm128(
    int M, int N, int K,
    const float* __restrict__ A, const float* __restrict__ B,
    const float* __restrict__ bias, const float* __restrict__ prelu_a,
    const float* __restrict__ dinvp,
    float* __restrict__ C, __half* __restrict__ Ch)
{
    constexpr int BK = 16;
    constexpr int LDSA = 20;
    constexpr int LDSN = 136;
    __shared__ float As[2][128 * LDSA];
    __shared__ float Bs[2][BK * LDSN];

    const int tid  = threadIdx.x;
    const int lane = tid & 31;
    const int wid  = tid >> 5;
    const int g    = lane >> 2;
    const int t    = lane & 3;

    const int warpM = (wid & 1) * 64;
    const int warpN = (wid >> 1) * 32;

    const int gRow = blockIdx.y * 128;
    const int gCol = blockIdx.x * 128;

    auto issueTile = [&](int k0, int s) {
#pragma unroll
        for (int i = 0; i < 2; i++) {
            int idx = tid + i * 256;
            int m  = idx >> 2, kq = (idx & 3) << 2;
            int gm = gRow + m;
            cp16(&As[s][m * LDSA + kq], &A[(size_t)gm * K + k0 + kq], gm < M);
        }
#pragma unroll
        for (int i = 0; i < 2; i++) {
            int idx = tid + i * 256;
            int k = idx >> 5, n4 = (idx & 31) << 2;
            cp16(&Bs[s][k * LDSN + n4], &B[(size_t)(k0 + k) * N + gCol + n4], true);
        }
    };

    float c[4][4][4];
#pragma unroll
    for (int mt = 0; mt < 4; mt++)
#pragma unroll
        for (int nt = 0; nt < 4; nt++)
#pragma unroll
            for (int i = 0; i < 4; i++) c[mt][nt][i] = 0.f;

    const int T = K / BK;
    issueTile(0, 0);
    CP_COMMIT;

    for (int it = 0; it < T; it++) {
        int s = it & 1;
        if (it + 1 < T) {
            issueTile((it + 1) * BK, s ^ 1);
            CP_COMMIT;
            CP_WAIT(1);
        } else {
            CP_WAIT(0);
        }
        __syncthreads();

#pragma unroll
        for (int kk = 0; kk < BK; kk += 8) {
            uint32_t af[4][4], bf[4][2];
#pragma unroll
            for (int mt = 0; mt < 4; mt++) {
                int m0 = warpM + mt * 16 + g;
                af[mt][0] = f2tf32(As[s][(m0    ) * LDSA + kk + t    ]);
                af[mt][1] = f2tf32(As[s][(m0 + 8) * LDSA + kk + t    ]);
                af[mt][2] = f2tf32(As[s][(m0    ) * LDSA + kk + t + 4]);
                af[mt][3] = f2tf32(As[s][(m0 + 8) * LDSA + kk + t + 4]);
            }
#pragma unroll
            for (int nt = 0; nt < 4; nt++) {
                int n0 = warpN + nt * 8 + g;
                bf[nt][0] = f2tf32(Bs[s][(kk + t    ) * LDSN + n0]);
                bf[nt][1] = f2tf32(Bs[s][(kk + t + 4) * LDSN + n0]);
            }
#pragma unroll
            for (int mt = 0; mt < 4; mt++)
#pragma unroll
                for (int nt = 0; nt < 4; nt++)
                    mma_tf32(c[mt][nt], af[mt], bf[nt]);
        }
        __syncthreads();
    }

    float a_val = 0.f;
    if (EPI == 1) a_val = *prelu_a;

#pragma unroll
    for (int mt = 0; mt < 4; mt++) {
        int r0 = gRow + warpM + mt * 16 + g;
        int r1 = r0 + 8;
        float s0 = 1.f, s1 = 1.f;
        if (EPI == 5) {
            if (r0 < M) s0 = dinvp[r0];
            if (r1 < M) s1 = dinvp[r1];
        }
#pragma unroll
        for (int nt = 0; nt < 4; nt++) {
            int col = gCol + warpN + nt * 8 + t * 2;
            float v0 = c[mt][nt][0], v1 = c[mt][nt][1];
            float v2 = c[mt][nt][2], v3 = c[mt][nt][3];

            if (EPI == 1 || EPI == 2 || EPI == 3) {
                float b0 = bias[col], b1 = bias[col + 1];
                v0 += b0; v1 += b1; v2 += b0; v3 += b1;
            }
            if (EPI == 1) {
                v0 = v0 >= 0.f ? v0 : a_val * v0;
                v1 = v1 >= 0.f ? v1 : a_val * v1;
                v2 = v2 >= 0.f ? v2 : a_val * v2;
                v3 = v3 >= 0.f ? v3 : a_val * v3;
            }
            if (EPI == 2) {
                v0 = fmaxf(v0, 0.f); v1 = fmaxf(v1, 0.f);
                v2 = fmaxf(v2, 0.f); v3 = fmaxf(v3, 0.f);
            }

            if (EPI == 5) {
                if (r0 < M)
                    *reinterpret_cast<__half2*>(&Ch[(size_t)r0 * N + col]) =
                        __floats2half2_rn(v0 * s0, v1 * s0);
                if (r1 < M)
                    *reinterpret_cast<__half2*>(&Ch[(size_t)r1 * N + col]) =
                        __floats2half2_rn(v2 * s1, v3 * s1);
            } else {
                if (r0 < M)
                    *reinterpret_cast<float2*>(&C[(size_t)r0 * N + col]) = make_float2(v0, v1);
                if (r1 < M)
                    *reinterpret_cast<float2*>(&C[(size_t)r1 * N + col]) = make_float2(v2, v3);
            }
        }
    }
}

// ---- fused proj head: proj = relu(A@fc1 + b1h) @ fc2 + b2h, hidden in smem ----
__global__ __launch_bounds__(256) void k_proj(
    int M,
    const float* __restrict__ A,
    const float* __restrict__ fc1w, const float* __restrict__ fc1b,
    const float* __restrict__ fc2w, const float* __restrict__ fc2b,
    float* __restrict__ C)
{
    constexpr int BK = 16, LDSA = 20, LDSN = 136, LDH = 132, K = 128, N = 128;
    extern __shared__ float sm[];
    float* As = sm;
    float* Bs = As + 2 * 128 * LDSA;
    float* H  = Bs + 2 * BK * LDSN;

    const int tid  = threadIdx.x;
    const int lane = tid & 31;
    const int wid  = tid >> 5;
    const int g    = lane >> 2;
    const int t    = lane & 3;
    const int warpM = (wid & 1) * 64;
    const int warpN = (wid >> 1) * 32;
    const int gRow = blockIdx.y * 128;

    auto issueA = [&](int k0, int s) {
#pragma unroll
        for (int i = 0; i < 2; i++) {
            int idx = tid + i * 256;
            int m = idx >> 2, kq = (idx & 3) << 2;
            int gm = gRow + m;
            cp16(&As[s * 128 * LDSA + m * LDSA + kq], &A[(size_t)gm * K + k0 + kq], gm < M);
        }
    };
    auto issueB = [&](const float* B, int k0, int s) {
#pragma unroll
        for (int i = 0; i < 2; i++) {
            int idx = tid + i * 256;
            int k = idx >> 5, n4 = (idx & 31) << 2;
            cp16(&Bs[s * BK * LDSN + k * LDSN + n4], &B[(size_t)(k0 + k) * N + n4], true);
        }
    };

    float c[4][4][4];
    auto zeroC = [&]() {
#pragma unroll
        for (int mt = 0; mt < 4; mt++)
#pragma unroll
            for (int nt = 0; nt < 4; nt++)
#pragma unroll
                for (int i = 0; i < 4; i++) c[mt][nt][i] = 0.f;
    };

    // stage 1: H = relu(A @ fc1 + fc1b)
    zeroC();
    issueA(0, 0); issueB(fc1w, 0, 0);
    CP_COMMIT;
    const int T = K / BK;
    for (int it = 0; it < T; it++) {
        int s = it & 1;
        if (it + 1 < T) {
            issueA((it + 1) * BK, s ^ 1); issueB(fc1w, (it + 1) * BK, s ^ 1);
            CP_COMMIT; CP_WAIT(1);
        } else CP_WAIT(0);
        __syncthreads();
#pragma unroll
        for (int kk = 0; kk < BK; kk += 8) {
            uint32_t af[4][4], bf[4][2];
#pragma unroll
            for (int mt = 0; mt < 4; mt++) {
                int m0 = warpM + mt * 16 + g;
                const float* Ab = &As[s * 128 * LDSA];
                af[mt][0] = f2tf32(Ab[(m0    ) * LDSA + kk + t    ]);
                af[mt][1] = f2tf32(Ab[(m0 + 8) * LDSA + kk + t    ]);
                af[mt][2] = f2tf32(Ab[(m0    ) * LDSA + kk + t + 4]);
                af[mt][3] = f2tf32(Ab[(m0 + 8) * LDSA + kk + t + 4]);
            }
#pragma unroll
            for (int nt = 0; nt < 4; nt++) {
                int n0 = warpN + nt * 8 + g;
                const float* Bb = &Bs[s * BK * LDSN];
                bf[nt][0] = f2tf32(Bb[(kk + t    ) * LDSN + n0]);
                bf[nt][1] = f2tf32(Bb[(kk + t + 4) * LDSN + n0]);
            }
#pragma unroll
            for (int mt = 0; mt < 4; mt++)
#pragma unroll
                for (int nt = 0; nt < 4; nt++)
                    mma_tf32(c[mt][nt], af[mt], bf[nt]);
        }
        __syncthreads();
    }
#pragma unroll
    for (int mt = 0; mt < 4; mt++) {
        int m0 = warpM + mt * 16 + g;
#pragma unroll
        for (int nt = 0; nt < 4; nt++) {
            int col = warpN + nt * 8 + t * 2;
            float b0 = fc1b[col], b1 = fc1b[col + 1];
            float v0 = fmaxf(c[mt][nt][0] + b0, 0.f);
            float v1 = fmaxf(c[mt][nt][1] + b1, 0.f);
            float v2 = fmaxf(c[mt][nt][2] + b0, 0.f);
            float v3 = fmaxf(c[mt][nt][3] + b1, 0.f);
            *reinterpret_cast<float2*>(&H[(m0    ) * LDH + col]) = make_float2(v0, v1);
            *reinterpret_cast<float2*>(&H[(m0 + 8) * LDH + col]) = make_float2(v2, v3);
        }
    }
    __syncthreads();

    // stage 2: C = H @ fc2 + fc2b
    zeroC();
    issueB(fc2w, 0, 0);
    CP_COMMIT;
    for (int it = 0; it < T; it++) {
        int s = it & 1;
        if (it + 1 < T) {
            issueB(fc2w, (it + 1) * BK, s ^ 1);
            CP_COMMIT; CP_WAIT(1);
        } else CP_WAIT(0);
        __syncthreads();
        int kbase = it * BK;
#pragma unroll
        for (int kk = 0; kk < BK; kk += 8) {
            uint32_t af[4][4], bf[4][2];
#pragma unroll
            for (int mt = 0; mt < 4; mt++) {
                int m0 = warpM + mt * 16 + g;
                af[mt][0] = f2tf32(H[(m0    ) * LDH + kbase + kk + t    ]);
                af[mt][1] = f2tf32(H[(m0 + 8) * LDH + kbase + kk + t    ]);
                af[mt][2] = f2tf32(H[(m0    ) * LDH + kbase + kk + t + 4]);
                af[mt][3] = f2tf32(H[(m0 + 8) * LDH + kbase + kk + t + 4]);
            }
#pragma unroll
            for (int nt = 0; nt < 4; nt++) {
                int n0 = warpN + nt * 8 + g;
                const float* Bb = &Bs[s * BK * LDSN];
                bf[nt][0] = f2tf32(Bb[(kk + t    ) * LDSN + n0]);
                bf[nt][1] = f2tf32(Bb[(kk + t + 4) * LDSN + n0]);
            }
#pragma unroll
            for (int mt = 0; mt < 4; mt++)
#pragma unroll
                for (int nt = 0; nt < 4; nt++)
                    mma_tf32(c[mt][nt], af[mt], bf[nt]);
        }
        __syncthreads();
    }
#pragma unroll
    for (int mt = 0; mt < 4; mt++) {
        int r0 = gRow + warpM + mt * 16 + g;
        int r1 = r0 + 8;
#pragma unroll
        for (int nt = 0; nt < 4; nt++) {
            int col = warpN + nt * 8 + t * 2;
            float b0 = fc2b[col], b1 = fc2b[col + 1];
            if (r0 < M)
                *reinterpret_cast<float2*>(&C[(size_t)r0 * N + col]) =
                    make_float2(c[mt][nt][0] + b0, c[mt][nt][1] + b1);
            if (r1 < M)
                *reinterpret_cast<float2*>(&C[(size_t)r1 * N + col]) =
                    make_float2(c[mt][nt][2] + b0, c[mt][nt][3] + b1);
        }
    }
}

// ---------------- launch ----------------
extern "C" void kernel_launch(void* const* d_in, const int* in_sizes, int n_in,
                              void* d_out, int out_size) {
    const float* x    = (const float*)d_in[0];
    const int*   ei   = (const int*)d_in[1];
    const float* W1   = (const float*)d_in[2];
    const float* b1   = (const float*)d_in[3];
    const float* W2   = (const float*)d_in[4];
    const float* b2   = (const float*)d_in[5];
    const float* a    = (const float*)d_in[6];
    const float* fc1w = (const float*)d_in[7];
    const float* fc1b = (const float*)d_in[8];
    const float* fc2w = (const float*)d_in[9];
    const float* fc2b = (const float*)d_in[10];

    const int N = in_sizes[0] / 128;      // 100000 nodes
    const int E = in_sizes[1] / 2;        // 1600000 edges
    const int* src = ei;
    const int* dst = ei + E;

    float* out  = (float*)d_out;                    // [N,128]
    float* proj = out + (size_t)N * 128;            // [N,128]

    float *pd, *pagg, *pout1;
    __half* ph16;
    int *pdeg, *pexcl, *pbtot, *prowp, *pcur, *pcsrc;
    cudaGetSymbolAddress((void**)&pd,    g_dinv);
    cudaGetSymbolAddress((void**)&pagg,  g_agg);
    cudaGetSymbolAddress((void**)&pout1, g_out1);
    cudaGetSymbolAddress((void**)&ph16,  g_h16);
    cudaGetSymbolAddress((void**)&pdeg,  g_deg);
    cudaGetSymbolAddress((void**)&pexcl, g_excl);
    cudaGetSymbolAddress((void**)&pbtot, g_btot);
    cudaGetSymbolAddress((void**)&prowp, g_rowp);
    cudaGetSymbolAddress((void**)&pcur,  g_cur);
    cudaGetSymbolAddress((void**)&pcsrc, g_csrc);

    const int TPB = 256;
    const int nb  = (N + SCAN_B - 1) / SCAN_B;
    const int n4  = N * 32;
    const int aggBlocks = (N * 32 + TPB - 1) / TPB;
    const int projSmem = (2 * 128 * 20 + 2 * 16 * 136 + 128 * 132) * 4;

    cudaFuncSetAttribute(k_proj, cudaFuncAttributeMaxDynamicSharedMemorySize, projSmem);

    // ---- CSR build (dinv needed before prescaled f2h) ----
    k_hist<<<(E + TPB - 1) / TPB, TPB>>>(dst, pdeg, E);
    k_scan_blocks<<<nb, SCAN_B>>>(pdeg, pexcl, pbtot, N);
    k_scan_tops<<<1, 128>>>(pbtot, nb);
    k_finalize<<<(N + TPB - 1) / TPB, TPB>>>(pdeg, pexcl, pbtot, prowp, pcur, pd, N);
    k_f2h_scaled<<<(n4 + TPB - 1) / TPB, TPB>>>(x, pd, ph16, n4);
    k_fillcsr<<<(E + TPB - 1) / TPB, TPB>>>(src, dst, pcur, pcsrc, E);

    // ---- layer 1: agg(prescaled x16) -> fp32 ; GEMM1 ----
    k_agg16<false><<<aggBlocks, TPB>>>(prowp, pcsrc, pd, ph16, pagg,
                                       nullptr, nullptr, nullptr, N);
    dim3 grid1(2, (N + 127) / 128);
    dim3 grid2(1, (N + 127) / 128);
    tgemm128<1><<<grid1, 256>>>(N, 256, 128, pagg, W1, b1, a, nullptr, pout1, nullptr);

    // ---- layer 2: h2 = (out1 @ W2) * dinv stored fp16 ; agg final ----
    tgemm128<5><<<grid2, 256>>>(N, 128, 256, pout1, W2, nullptr, nullptr, pd, nullptr, ph16);
    k_agg16<true><<<aggBlocks, TPB>>>(prowp, pcsrc, pd, ph16, pagg,
                                      b2, a, out, N);

    // ---- fused proj head ----
    k_proj<<<grid2, 256, projSmem>>>(N, pagg, fc1w, fc1b, fc2w, fc2b, proj);
}